// round 2
// baseline (speedup 1.0000x reference)
#include <cuda_runtime.h>
#include <math.h>
#include <stdint.h>

// Problem constants
#define Bn   16384
#define OBSn 376
#define Hn   512
#define Mn   8
#define L1n  3
#define Tn   50
#define An   17
#define LOGS2PI 0.9189385332046727f

// ---------------- scratch (device globals; no allocation allowed) ----------------
__device__ float d_h1[(size_t)Bn * Hn];          // encoder hidden
__device__ float d_fs[(size_t)Bn * Hn];          // f_s
__device__ float d_rel[(size_t)Bn * Hn];         // relu(f_s * emb[idx])
__device__ float d_probsA[(size_t)Bn * L1n * 64];
__device__ float d_probsC[(size_t)Bn * L1n * 64];
__device__ float d_outs[(size_t)Bn * Mn * Hn];   // per-layer module outputs
__device__ float d_g0[(size_t)Bn * Mn * Hn];
__device__ float d_g1[(size_t)Bn * Mn * Hn];
__device__ float d_g2[(size_t)Bn * Mn * Hn];     // critic final g
__device__ float d_actorOut[(size_t)Bn * An];
__device__ float d_val[Bn];
__device__ float d_cst[32];                      // [0..16]=sum_m a_bf, [17]=log_prob, [18]=entropy, [19]=sum_m c_bf
__device__ int   d_is64;

// ---------------- task_idx dtype detector ----------------
// If buffer is int64 (LE) with values in [0,50): int32 words look like [v,0,v,0,...]
// -> all odd words zero, even words in range. If int32: odd words are task ids,
// P(all 512 odd words == 0) ~ (1/50)^512 == never.
__global__ void detect_kernel(const int* __restrict__ ti) {
    __shared__ int ok;
    if (threadIdx.x == 0) ok = 1;
    __syncthreads();
    for (int i = threadIdx.x; i < 1024; i += blockDim.x) {
        int v = ti[i];
        bool good = (i & 1) ? (v == 0) : (v >= 0 && v < Tn);
        if (!good) atomicAnd(&ok, 0);
    }
    __syncthreads();
    if (threadIdx.x == 0) d_is64 = ok;
}

// ---------------- generic fp32 GEMM: C = act(A[M,K] @ B[K,N] + bias) ----------------
// Tiles: BM=64, BN=64, BK=8, 256 threads, 4x4 per-thread micro tile.
// Requirements used here: M % 64 == 0 (always 16384), K % 8 == 0 (376/512/4096),
// lda even (float2 A loads). N guarded (17/64/512).
template<int ACT>  // 0=none, 1=relu, 2=tanh
__global__ __launch_bounds__(256) void gemm_kernel(
    const float* __restrict__ A, int lda,
    const float* __restrict__ Bm, int ldb,
    const float* __restrict__ bias,
    float* __restrict__ C, int ldc,
    int N, int K)
{
    __shared__ __align__(16) float As[8][64];   // [k][m]
    __shared__ __align__(16) float Bs[8][64];   // [k][n]
    const int t  = threadIdx.x;
    const int m0 = blockIdx.x * 64;
    const int n0 = blockIdx.y * 64;

    const int arow = t >> 2;          // 0..63
    const int akp  = (t & 3) * 2;     // 0,2,4,6
    const int bk0  = t >> 6;          // 0..3
    const int bc   = t & 63;          // 0..63
    const int tr   = t >> 4;          // 0..15
    const int tc   = t & 15;          // 0..15

    float acc[4][4];
#pragma unroll
    for (int i = 0; i < 4; i++)
#pragma unroll
        for (int j = 0; j < 4; j++) acc[i][j] = 0.f;

    const int nt = K >> 3;
    const float* Arow = A + (size_t)(m0 + arow) * lda;
    const int n_g = n0 + bc;
    const bool nok = (n_g < N);

    float2 ra; float rb0, rb1;
    // prefetch tile 0
    ra  = *(const float2*)(Arow + akp);
    rb0 = nok ? Bm[(size_t)bk0 * ldb + n_g] : 0.f;
    rb1 = nok ? Bm[(size_t)(bk0 + 4) * ldb + n_g] : 0.f;

    for (int kt = 0; kt < nt; ++kt) {
        As[akp][arow]     = ra.x;
        As[akp + 1][arow] = ra.y;
        Bs[bk0][bc]       = rb0;
        Bs[bk0 + 4][bc]   = rb1;
        __syncthreads();

        if (kt + 1 < nt) {
            const int kb = (kt + 1) << 3;
            ra = *(const float2*)(Arow + kb + akp);
            if (nok) {
                rb0 = Bm[(size_t)(kb + bk0) * ldb + n_g];
                rb1 = Bm[(size_t)(kb + bk0 + 4) * ldb + n_g];
            } else { rb0 = 0.f; rb1 = 0.f; }
        }

#pragma unroll
        for (int kk = 0; kk < 8; ++kk) {
            float4 av = *(const float4*)&As[kk][tr * 4];
            float4 bv = *(const float4*)&Bs[kk][tc * 4];
            float aa[4] = {av.x, av.y, av.z, av.w};
            float bb[4] = {bv.x, bv.y, bv.z, bv.w};
#pragma unroll
            for (int i = 0; i < 4; i++)
#pragma unroll
                for (int j = 0; j < 4; j++)
                    acc[i][j] = fmaf(aa[i], bb[j], acc[i][j]);
        }
        __syncthreads();
    }

#pragma unroll
    for (int j = 0; j < 4; j++) {
        const int n = n0 + tc * 4 + j;
        if (n < N) {
            const float bv = bias ? bias[n] : 0.f;
#pragma unroll
            for (int i = 0; i < 4; i++) {
                float v = acc[i][j] + bv;
                if (ACT == 1) v = fmaxf(v, 0.f);
                if (ACT == 2) v = tanhf(v);
                C[(size_t)(m0 + tr * 4 + i) * ldc + n] = v;
            }
        }
    }
}

// ---------------- rel = relu(f_s * task_emb[task_idx]) ----------------
__global__ void rel_kernel(const float* __restrict__ fs, const void* __restrict__ tidx,
                           const float* __restrict__ emb, float* __restrict__ rel) {
    const int gid = blockIdx.x * blockDim.x + threadIdx.x;  // Bn*128
    const int b  = gid >> 7;
    const int h4 = gid & 127;
    long long ti;
    if (d_is64) ti = ((const long long*)tidx)[b];
    else        ti = (long long)((const int*)tidx)[b];
    float4 f = *(const float4*)(fs + (size_t)b * Hn + h4 * 4);
    float4 e = *(const float4*)(emb + (size_t)ti * Hn + h4 * 4);
    float4 r;
    r.x = fmaxf(f.x * e.x, 0.f);
    r.y = fmaxf(f.y * e.y, 0.f);
    r.z = fmaxf(f.z * e.z, 0.f);
    r.w = fmaxf(f.w * e.w, 0.f);
    *(float4*)(rel + (size_t)b * Hn + h4 * 4) = r;
}

// ---------------- softmax over groups of 8 (in place), both nets ----------------
__global__ void softmax_kernel(float* __restrict__ pA, float* __restrict__ pC) {
    const int gid = blockIdx.x * blockDim.x + threadIdx.x;   // 2*Bn*24
    const int per = Bn * L1n * 8;
    float* p = (gid < per) ? (pA + (size_t)gid * 8) : (pC + (size_t)(gid - per) * 8);
    float v[8], mx = -1e30f;
#pragma unroll
    for (int j = 0; j < 8; j++) { v[j] = p[j]; mx = fmaxf(mx, v[j]); }
    float s = 0.f;
#pragma unroll
    for (int j = 0; j < 8; j++) { v[j] = __expf(v[j] - mx); s += v[j]; }
    const float inv = 1.f / s;
#pragma unroll
    for (int j = 0; j < 8; j++) p[j] = v[j] * inv;
}

// ---------------- mix: g'[b,i,h] = sum_j p[b,i,j] * outs[b,j,h] ----------------
// probs points at layer slice; row stride 192. 128 threads/block, block = one b.
__global__ void mix_kernel(const float* __restrict__ probs, const float* __restrict__ outs,
                           float* __restrict__ gout) {
    __shared__ float p[64];
    const int b = blockIdx.x;
    const int tid = threadIdx.x;
    if (tid < 64) p[tid] = probs[(size_t)b * (L1n * 64) + tid];
    __syncthreads();
    const float* ob = outs + (size_t)b * (Mn * Hn);
    float4 o[8];
#pragma unroll
    for (int j = 0; j < 8; j++)
        o[j] = *(const float4*)(ob + j * Hn + tid * 4);
#pragma unroll
    for (int i = 0; i < 8; i++) {
        float4 a = make_float4(0.f, 0.f, 0.f, 0.f);
#pragma unroll
        for (int j = 0; j < 8; j++) {
            const float w = p[i * 8 + j];
            a.x = fmaf(w, o[j].x, a.x);
            a.y = fmaf(w, o[j].y, a.y);
            a.z = fmaf(w, o[j].z, a.z);
            a.w = fmaf(w, o[j].w, a.w);
        }
        *(float4*)(gout + (size_t)b * (Mn * Hn) + i * Hn + tid * 4) = a;
    }
}

// ---------------- critic final: val[b] = sum_{m,h} g[b,m,h]*c_Wf[m,h] ----------------
__global__ void critic_kernel(const float* __restrict__ g, const float* __restrict__ wf,
                              float* __restrict__ val) {
    const int w    = (blockIdx.x * blockDim.x + threadIdx.x) >> 5;
    const int lane = threadIdx.x & 31;
    const float* gr = g + (size_t)w * (Mn * Hn);
    float s = 0.f;
    for (int i = lane; i < Mn * Hn; i += 32) s = fmaf(gr[i], wf[i], s);
#pragma unroll
    for (int off = 16; off > 0; off >>= 1) s += __shfl_xor_sync(0xFFFFFFFFu, s, off);
    if (lane == 0) val[w] = s;
}

// ---------------- constants: summed final biases + logstd reductions ----------------
__global__ void prep_kernel(const float* __restrict__ abf, const float* __restrict__ cbf,
                            const float* __restrict__ logstd) {
    const int t = threadIdx.x;
    if (t < An) {
        float s = 0.f;
        for (int m = 0; m < Mn; m++) s += abf[m * An + t];
        d_cst[t] = s;
    }
    if (t == 17) {
        float s = 0.f;
        for (int m = 0; m < Mn; m++) s += cbf[m];
        d_cst[19] = s;
    }
    if (t == 18) {
        float lp = 0.f, en = 0.f;
        for (int a = 0; a < An; a++) {
            lp += -logstd[a] - LOGS2PI;
            en += 0.5f + LOGS2PI + logstd[a];
        }
        d_cst[17] = lp;
        d_cst[18] = en;
    }
}

// ---------------- pack output: [mean(17), log_prob, entropy, value] ----------------
__global__ void pack_kernel(const float* __restrict__ actorOut, const float* __restrict__ val,
                            float* __restrict__ out) {
    const int gid = blockIdx.x * blockDim.x + threadIdx.x;   // Bn*20
    const int b = gid / 20, k = gid % 20;
    float v;
    if (k < An)        v = actorOut[(size_t)b * An + k];
    else if (k == 17)  v = d_cst[17];
    else if (k == 18)  v = d_cst[18];
    else               v = val[b] + d_cst[19];
    out[gid] = v;
}

// ---------------- host ----------------
extern "C" void kernel_launch(void* const* d_in, const int* in_sizes, int n_in,
                              void* d_out, int out_size) {
    const float* x      = (const float*)d_in[0];
    const void*  tidx   = d_in[1];
    const float* W1     = (const float*)d_in[2];
    const float* b1     = (const float*)d_in[3];
    const float* W2     = (const float*)d_in[4];
    const float* b2     = (const float*)d_in[5];
    const float* emb    = (const float*)d_in[6];
    const float* a_rW   = (const float*)d_in[7];
    const float* a_rb   = (const float*)d_in[8];
    const float* c_rW   = (const float*)d_in[9];
    const float* c_rb   = (const float*)d_in[10];
    const float* a_W    = (const float*)d_in[11];
    const float* a_b    = (const float*)d_in[12];
    const float* a_Wf   = (const float*)d_in[13];
    const float* a_bf   = (const float*)d_in[14];
    const float* c_W    = (const float*)d_in[15];
    const float* c_b    = (const float*)d_in[16];
    const float* c_Wf   = (const float*)d_in[17];
    const float* c_bf   = (const float*)d_in[18];
    const float* logstd = (const float*)d_in[19];
    float* out = (float*)d_out;

    float *h1, *fs, *rel, *pA, *pC, *outs, *g0, *g1, *g2, *actorOut, *val, *cst;
    cudaGetSymbolAddress((void**)&h1, d_h1);
    cudaGetSymbolAddress((void**)&fs, d_fs);
    cudaGetSymbolAddress((void**)&rel, d_rel);
    cudaGetSymbolAddress((void**)&pA, d_probsA);
    cudaGetSymbolAddress((void**)&pC, d_probsC);
    cudaGetSymbolAddress((void**)&outs, d_outs);
    cudaGetSymbolAddress((void**)&g0, d_g0);
    cudaGetSymbolAddress((void**)&g1, d_g1);
    cudaGetSymbolAddress((void**)&g2, d_g2);
    cudaGetSymbolAddress((void**)&actorOut, d_actorOut);
    cudaGetSymbolAddress((void**)&val, d_val);
    cudaGetSymbolAddress((void**)&cst, d_cst);

    const dim3 gFull(Bn / 64, Hn / 64);   // M=16384, N=512
    const dim3 gN64(Bn / 64, 1);          // N<=64

    detect_kernel<<<1, 256>>>((const int*)tidx);

    // Encoder: h1 = tanh(x @ W1 + b1); fs = tanh(h1 @ W2 + b2)
    gemm_kernel<2><<<gFull, 256>>>(x, OBSn, W1, Hn, b1, h1, Hn, Hn, OBSn);
    gemm_kernel<2><<<gFull, 256>>>(h1, Hn, W2, Hn, b2, fs, Hn, Hn, Hn);

    rel_kernel<<<(Bn * 128) / 256, 256>>>(fs, tidx, emb, rel);

    // Routing logits -> probs buffers, both nets, per layer
    for (int l = 0; l < L1n; l++) {
        gemm_kernel<0><<<gN64, 256>>>(rel, Hn, a_rW + (size_t)l * Hn * 64, 64,
                                      a_rb + (size_t)l * 64, pA + (size_t)l * 64,
                                      L1n * 64, 64, Hn);
        gemm_kernel<0><<<gN64, 256>>>(rel, Hn, c_rW + (size_t)l * Hn * 64, 64,
                                      c_rb + (size_t)l * 64, pC + (size_t)l * 64,
                                      L1n * 64, 64, Hn);
    }
    softmax_kernel<<<(2 * Bn * L1n * 8) / 256, 256>>>(pA, pC);

    // Base networks: critic uses pC -> g2 final; actor uses pA -> g0 final.
    // Critic chain: fs -> g0 -> g1 -> g2
    {
        const float* gprev = fs;
        float* gs[3] = {g0, g1, g2};
        for (int l = 0; l < L1n; l++) {
            for (int m = 0; m < Mn; m++) {
                const float* Aptr = (l == 0) ? fs : (gprev + (size_t)m * Hn);
                const int lda = (l == 0) ? Hn : (Mn * Hn);
                gemm_kernel<1><<<gFull, 256>>>(
                    Aptr, lda,
                    c_W + (size_t)(l * Mn + m) * Hn * Hn, Hn,
                    c_b + (size_t)(l * Mn + m) * Hn,
                    outs + (size_t)m * Hn, Mn * Hn, Hn, Hn);
            }
            mix_kernel<<<Bn, 128>>>(pC + (size_t)l * 64, outs, gs[l]);
            gprev = gs[l];
        }
    }
    // Actor chain: fs -> g0 -> g1 -> g0  (g2 holds critic final, untouched)
    {
        const float* gprev = fs;
        float* gs[3] = {g0, g1, g0};
        for (int l = 0; l < L1n; l++) {
            for (int m = 0; m < Mn; m++) {
                const float* Aptr = (l == 0) ? fs : (gprev + (size_t)m * Hn);
                const int lda = (l == 0) ? Hn : (Mn * Hn);
                gemm_kernel<1><<<gFull, 256>>>(
                    Aptr, lda,
                    a_W + (size_t)(l * Mn + m) * Hn * Hn, Hn,
                    a_b + (size_t)(l * Mn + m) * Hn,
                    outs + (size_t)m * Hn, Mn * Hn, Hn, Hn);
            }
            mix_kernel<<<Bn, 128>>>(pA + (size_t)l * 64, outs, gs[l]);
            gprev = gs[l];
        }
    }

    prep_kernel<<<1, 32>>>(a_bf, c_bf, logstd);

    // Actor final: [B, 8*512] @ [8*512, 17] + sum_m a_bf
    gemm_kernel<0><<<gN64, 256>>>(g0, Mn * Hn, a_Wf, An, cst, actorOut, An, An, Mn * Hn);
    // Critic final: dot per row
    critic_kernel<<<Bn / 8, 256>>>(g2, c_Wf, val);

    pack_kernel<<<(Bn * 20) / 256, 256>>>(actorOut, val, out);
}

// round 4
// speedup vs baseline: 3.3361x; 3.3361x over previous
#include <cuda_runtime.h>
#include <cuda_bf16.h>
#include <math.h>
#include <stdint.h>

#define Bn   16384
#define OBSn 376
#define Hn   512
#define Mn   8
#define L1n  3
#define Tn   50
#define An   17
#define LOGS2PI 0.9189385332046727f

// ===================== helpers =====================
__device__ __forceinline__ uint32_t smem_to_u32(const void* p) {
    uint32_t a;
    asm("{ .reg .u64 t; cvta.to.shared.u64 t, %1; cvt.u32.u64 %0, t; }" : "=r"(a) : "l"(p));
    return a;
}
#define LDSM4(r0, r1, r2, r3, addr) \
    asm volatile("ldmatrix.sync.aligned.m8n8.x4.shared.b16 {%0,%1,%2,%3}, [%4];" \
        : "=r"(r0), "=r"(r1), "=r"(r2), "=r"(r3) : "r"(addr))
#define MMA16816(d, a, b0v, b1v) \
    asm volatile("mma.sync.aligned.m16n8k16.row.col.f32.bf16.bf16.f32 " \
        "{%0,%1,%2,%3}, {%4,%5,%6,%7}, {%8,%9}, {%0,%1,%2,%3};" \
        : "+f"((d)[0]), "+f"((d)[1]), "+f"((d)[2]), "+f"((d)[3]) \
        : "r"((a)[0]), "r"((a)[1]), "r"((a)[2]), "r"((a)[3]), "r"(b0v), "r"(b1v))
#define CP_ASYNC16(dst, src) \
    asm volatile("cp.async.cg.shared.global [%0], [%1], 16;" :: "r"(dst), "l"(src) : "memory")
#define CP_COMMIT() asm volatile("cp.async.commit_group;" ::: "memory")
#define CP_WAIT0()  asm volatile("cp.async.wait_group 0;" ::: "memory")

__device__ __forceinline__ uint32_t pack2bf(float a, float b) {
    __nv_bfloat162 p = __floats2bfloat162_rn(a, b);
    return *reinterpret_cast<uint32_t*>(&p);
}
__device__ __forceinline__ float residf(float v) {
    return v - __bfloat162float(__float2bfloat16(v));
}

// ===================== scratch =====================
__device__ float d_h1[(size_t)Bn * Hn];
__device__ float d_fs[(size_t)Bn * Hn];
__device__ float d_rel[(size_t)Bn * Hn];
__device__ float d_probsA[(size_t)Bn * L1n * 64];
__device__ float d_probsC[(size_t)Bn * L1n * 64];
__device__ float d_outs[(size_t)Bn * Mn * Hn];
__device__ float d_g0[(size_t)Bn * Mn * Hn];
__device__ float d_g1[(size_t)Bn * Mn * Hn];
__device__ float d_g2[(size_t)Bn * Mn * Hn];
__device__ float d_actorOut[(size_t)Bn * An];
__device__ float d_val[Bn];
__device__ float d_cst[32];
__device__ int   d_is64;

// transposed/split weights: [slab][Nalloc][2*Kpad] bf16 (hi | lo)
__device__ __align__(16) __nv_bfloat16 wt_e1[(size_t)512 * 768];
__device__ __align__(16) __nv_bfloat16 wt_e2[(size_t)512 * 1024];
__device__ __align__(16) __nv_bfloat16 wt_ar[(size_t)3 * 64 * 1024];
__device__ __align__(16) __nv_bfloat16 wt_cr[(size_t)3 * 64 * 1024];
__device__ __align__(16) __nv_bfloat16 wt_a[(size_t)24 * 512 * 1024];
__device__ __align__(16) __nv_bfloat16 wt_c[(size_t)24 * 512 * 1024];
__device__ __align__(16) __nv_bfloat16 wt_af[(size_t)64 * 8192];

// ===================== task_idx dtype detector =====================
__global__ void detect_kernel(const int* __restrict__ ti) {
    __shared__ int ok;
    if (threadIdx.x == 0) ok = 1;
    __syncthreads();
    for (int i = threadIdx.x; i < 1024; i += blockDim.x) {
        int v = ti[i];
        bool good = (i & 1) ? (v == 0) : (v >= 0 && v < Tn);
        if (!good) atomicAnd(&ok, 0);
    }
    __syncthreads();
    if (threadIdx.x == 0) d_is64 = ok;
}

// ===================== weight transpose + split =====================
__global__ void tconv_kernel(const float* __restrict__ W, __nv_bfloat16* __restrict__ Wt,
                             int K, int Nsrc, int Kpad) {
    __shared__ float t[32][33];
    const int Nalloc = gridDim.y * 32;
    W  += (size_t)blockIdx.z * K * Nsrc;
    Wt += (size_t)blockIdx.z * Nalloc * 2 * Kpad;
    const int k0 = blockIdx.x * 32, n0 = blockIdx.y * 32;
    for (int i = threadIdx.y; i < 32; i += 8) {
        int k = k0 + i, n = n0 + threadIdx.x;
        t[i][threadIdx.x] = (k < K && n < Nsrc) ? W[(size_t)k * Nsrc + n] : 0.f;
    }
    __syncthreads();
    for (int i = threadIdx.y; i < 32; i += 8) {
        int n = n0 + i, k = k0 + threadIdx.x;
        if (k < Kpad) {
            float v = t[threadIdx.x][i];
            __nv_bfloat16 hi = __float2bfloat16(v);
            __nv_bfloat16 lo = __float2bfloat16(v - __bfloat162float(hi));
            size_t base = (size_t)n * 2 * Kpad;
            Wt[base + k] = hi;
            Wt[base + Kpad + k] = lo;
        }
    }
}

// ===================== mma.sync split-bf16 GEMM =====================
// C[:, n0g:n0g+NT] = act(A @ W + bias). CTA 128 x NT, 8 warps, K chunked by 64.
// smem per buf: A_hi(16K) | A_lo(16K) | B_hi(NT*128) | B_lo(NT*128).
// Swizzle within a 128B row: byte kb at row r lives at kb ^ ((r&7)<<4).
template<int NT, int WARPS_M, int ACT>  // ACT: 0 none, 1 relu, 2 tanh
__global__ __launch_bounds__(256, 1) void mmagemm(
    const float* __restrict__ A, int lda, long long a_bs,
    const __nv_bfloat16* __restrict__ Wt, int Kpad, long long w_bs,
    const float* __restrict__ bias, int b_bs,
    float* __restrict__ C, int ldc, long long c_bs,
    int N_STORE, int K)
{
    extern __shared__ char smem[];
    const uint32_t sb = smem_to_u32(smem);
    const int tid = threadIdx.x, wid = tid >> 5, lane = tid & 31;
    const int m0 = blockIdx.x * 128;
    const int n0g = blockIdx.y * NT;
    const int zb = blockIdx.z;
    A    += (size_t)zb * a_bs;
    Wt   += (size_t)zb * w_bs + (size_t)n0g * (2 * Kpad);
    bias += (size_t)zb * b_bs + n0g;
    C    += (size_t)zb * c_bs + n0g;

    constexpr int MT = 128 / (16 * WARPS_M);   // m16-tiles per warp (4 or 2)
    constexpr int BB = NT * 128;               // bytes per B region
    constexpr int BUFSZ = 32768 + 2 * BB;
    const int wm0 = (wid % WARPS_M) * (MT * 16);
    const int wn0 = (wid / WARPS_M) * 32;

    float acc[MT][4][4];
#pragma unroll
    for (int mt = 0; mt < MT; ++mt)
#pragma unroll
        for (int nt = 0; nt < 4; ++nt)
#pragma unroll
            for (int e = 0; e < 4; ++e) acc[mt][nt][e] = 0.f;

    float4 fA[8];
    const int NC = Kpad >> 6;

    auto loadA = [&](int c) {
        const int k0 = c << 6;
#pragma unroll
        for (int it = 0; it < 8; ++it) {
            const int idx = it * 256 + tid;
            const int r = idx >> 4, kq = (idx & 15) << 2, kg = k0 + kq;
            fA[it] = make_float4(0.f, 0.f, 0.f, 0.f);
            if (kg < K) fA[it] = *(const float4*)(A + (size_t)(m0 + r) * lda + kg);
        }
    };
    auto stsA = [&](int buf) {
#pragma unroll
        for (int it = 0; it < 8; ++it) {
            const int idx = it * 256 + tid;
            const int r = idx >> 4, kq = (idx & 15) << 2;
            uint2 hi, lo;
            hi.x = pack2bf(fA[it].x, fA[it].y);
            hi.y = pack2bf(fA[it].z, fA[it].w);
            lo.x = pack2bf(residf(fA[it].x), residf(fA[it].y));
            lo.y = pack2bf(residf(fA[it].z), residf(fA[it].w));
            const uint32_t off = (uint32_t)r * 128 + (((uint32_t)kq * 2) ^ (((uint32_t)r & 7) << 4));
            *(uint2*)(smem + (size_t)buf * BUFSZ + off)         = hi;
            *(uint2*)(smem + (size_t)buf * BUFSZ + 16384 + off) = lo;
        }
    };
    auto cpB = [&](int c, int buf) {
        const int k0h = c << 6;  // half offset
        const uint32_t dbase = sb + buf * BUFSZ + 32768;
#pragma unroll
        for (int it = 0; it < NT / 32; ++it) {
            const int seg = it * 256 + tid;
            const int r = seg >> 3;
            const int ks = (seg & 7) * 16;  // byte offset within row
            const uint32_t doff = (uint32_t)r * 128 + ((uint32_t)ks ^ (((uint32_t)r & 7) << 4));
            const __nv_bfloat16* srch = Wt + (size_t)r * (2 * Kpad) + k0h + (ks >> 1);
            CP_ASYNC16(dbase + doff, srch);
            CP_ASYNC16(dbase + BB + doff, srch + Kpad);
        }
        CP_COMMIT();
    };
    auto compute = [&](int buf) {
        const uint32_t ab  = sb + buf * BUFSZ;
        const uint32_t alb = ab + 16384;
        const uint32_t bb  = ab + 32768;
        const uint32_t blb = bb + BB;
        const uint32_t xm = ((uint32_t)lane & 7) << 4;
        const int ra = ((lane >> 3) & 1) * 8 + (lane & 7);
        const int ka = ((lane >> 4) & 1) * 16;
        const int rb = ((lane >> 4) & 1) * 8 + (lane & 7);
        const int kb = ((lane >> 3) & 1) * 16;
#pragma unroll
        for (int s = 0; s < 4; ++s) {
            const int ksb = s * 32;
            uint32_t Ah[MT][4], Al[MT][4], Bh[4][2], Bl[4][2];
#pragma unroll
            for (int mt = 0; mt < MT; ++mt) {
                const uint32_t off = (uint32_t)(wm0 + mt * 16 + ra) * 128 +
                                     (((uint32_t)(ksb + ka)) ^ xm);
                LDSM4(Ah[mt][0], Ah[mt][1], Ah[mt][2], Ah[mt][3], ab + off);
                LDSM4(Al[mt][0], Al[mt][1], Al[mt][2], Al[mt][3], alb + off);
            }
#pragma unroll
            for (int p = 0; p < 2; ++p) {
                const uint32_t off = (uint32_t)(wn0 + p * 16 + rb) * 128 +
                                     (((uint32_t)(ksb + kb)) ^ xm);
                LDSM4(Bh[2 * p][0], Bh[2 * p][1], Bh[2 * p + 1][0], Bh[2 * p + 1][1], bb + off);
                LDSM4(Bl[2 * p][0], Bl[2 * p][1], Bl[2 * p + 1][0], Bl[2 * p + 1][1], blb + off);
            }
#pragma unroll
            for (int mt = 0; mt < MT; ++mt)
#pragma unroll
                for (int nt = 0; nt < 4; ++nt)
                    MMA16816(acc[mt][nt], Ah[mt], Bh[nt][0], Bh[nt][1]);
#pragma unroll
            for (int mt = 0; mt < MT; ++mt)
#pragma unroll
                for (int nt = 0; nt < 4; ++nt)
                    MMA16816(acc[mt][nt], Al[mt], Bh[nt][0], Bh[nt][1]);
#pragma unroll
            for (int mt = 0; mt < MT; ++mt)
#pragma unroll
                for (int nt = 0; nt < 4; ++nt)
                    MMA16816(acc[mt][nt], Ah[mt], Bl[nt][0], Bl[nt][1]);
        }
    };

    // prologue
    loadA(0);
    cpB(0, 0);
    stsA(0);
    CP_WAIT0();
    __syncthreads();

    for (int c = 0; c < NC; ++c) {
        const int buf = c & 1;
        if (c + 1 < NC) { loadA(c + 1); cpB(c + 1, buf ^ 1); }
        compute(buf);
        if (c + 1 < NC) { stsA(buf ^ 1); CP_WAIT0(); }
        __syncthreads();
    }

    // epilogue
    const int rem = N_STORE - n0g;
    const int g = lane >> 2, t = lane & 3;
    const bool vec_ok = ((ldc & 1) == 0);
#pragma unroll
    for (int mt = 0; mt < MT; ++mt) {
#pragma unroll
        for (int nt = 0; nt < 4; ++nt) {
            const int col = wn0 + nt * 8 + t * 2;
            float bv0 = (col < rem)     ? bias[col]     : 0.f;
            float bv1 = (col + 1 < rem) ? bias[col + 1] : 0.f;
            float v0 = acc[mt][nt][0] + bv0, v1 = acc[mt][nt][1] + bv1;
            float v2 = acc[mt][nt][2] + bv0, v3 = acc[mt][nt][3] + bv1;
            if (ACT == 1) { v0 = fmaxf(v0, 0.f); v1 = fmaxf(v1, 0.f); v2 = fmaxf(v2, 0.f); v3 = fmaxf(v3, 0.f); }
            if (ACT == 2) { v0 = tanhf(v0); v1 = tanhf(v1); v2 = tanhf(v2); v3 = tanhf(v3); }
            const int row0 = m0 + wm0 + mt * 16 + g;
            if (col + 1 < rem && vec_ok) {
                *(float2*)(C + (size_t)row0 * ldc + col)       = make_float2(v0, v1);
                *(float2*)(C + (size_t)(row0 + 8) * ldc + col) = make_float2(v2, v3);
            } else {
                if (col < rem)     { C[(size_t)row0 * ldc + col] = v0;       C[(size_t)(row0 + 8) * ldc + col] = v2; }
                if (col + 1 < rem) { C[(size_t)row0 * ldc + col + 1] = v1;   C[(size_t)(row0 + 8) * ldc + col + 1] = v3; }
            }
        }
    }
}

// ===================== small kernels (known-good) =====================
__global__ void rel_kernel(const float* __restrict__ fs, const void* __restrict__ tidx,
                           const float* __restrict__ emb, float* __restrict__ rel) {
    const int gid = blockIdx.x * blockDim.x + threadIdx.x;
    const int b = gid >> 7, h4 = gid & 127;
    long long ti;
    if (d_is64) ti = ((const long long*)tidx)[b];
    else        ti = (long long)((const int*)tidx)[b];
    float4 f = *(const float4*)(fs + (size_t)b * Hn + h4 * 4);
    float4 e = *(const float4*)(emb + (size_t)ti * Hn + h4 * 4);
    float4 r;
    r.x = fmaxf(f.x * e.x, 0.f);
    r.y = fmaxf(f.y * e.y, 0.f);
    r.z = fmaxf(f.z * e.z, 0.f);
    r.w = fmaxf(f.w * e.w, 0.f);
    *(float4*)(rel + (size_t)b * Hn + h4 * 4) = r;
}

__global__ void softmax_kernel(float* __restrict__ pA, float* __restrict__ pC) {
    const int gid = blockIdx.x * blockDim.x + threadIdx.x;
    const int per = Bn * L1n * 8;
    float* p = (gid < per) ? (pA + (size_t)gid * 8) : (pC + (size_t)(gid - per) * 8);
    float v[8], mx = -1e30f;
#pragma unroll
    for (int j = 0; j < 8; j++) { v[j] = p[j]; mx = fmaxf(mx, v[j]); }
    float s = 0.f;
#pragma unroll
    for (int j = 0; j < 8; j++) { v[j] = __expf(v[j] - mx); s += v[j]; }
    const float inv = 1.f / s;
#pragma unroll
    for (int j = 0; j < 8; j++) p[j] = v[j] * inv;
}

__global__ void mix_kernel(const float* __restrict__ probs, const float* __restrict__ outs,
                           float* __restrict__ gout) {
    __shared__ float p[64];
    const int b = blockIdx.x, tid = threadIdx.x;
    if (tid < 64) p[tid] = probs[(size_t)b * (L1n * 64) + tid];
    __syncthreads();
    const float* ob = outs + (size_t)b * (Mn * Hn);
    float4 o[8];
#pragma unroll
    for (int j = 0; j < 8; j++) o[j] = *(const float4*)(ob + j * Hn + tid * 4);
#pragma unroll
    for (int i = 0; i < 8; i++) {
        float4 a = make_float4(0.f, 0.f, 0.f, 0.f);
#pragma unroll
        for (int j = 0; j < 8; j++) {
            const float w = p[i * 8 + j];
            a.x = fmaf(w, o[j].x, a.x);
            a.y = fmaf(w, o[j].y, a.y);
            a.z = fmaf(w, o[j].z, a.z);
            a.w = fmaf(w, o[j].w, a.w);
        }
        *(float4*)(gout + (size_t)b * (Mn * Hn) + i * Hn + tid * 4) = a;
    }
}

__global__ void critic_kernel(const float* __restrict__ g, const float* __restrict__ wf,
                              float* __restrict__ val) {
    const int w = (blockIdx.x * blockDim.x + threadIdx.x) >> 5;
    const int lane = threadIdx.x & 31;
    const float* gr = g + (size_t)w * (Mn * Hn);
    float s = 0.f;
    for (int i = lane; i < Mn * Hn; i += 32) s = fmaf(gr[i], wf[i], s);
#pragma unroll
    for (int off = 16; off > 0; off >>= 1) s += __shfl_xor_sync(0xFFFFFFFFu, s, off);
    if (lane == 0) val[w] = s;
}

__global__ void prep_kernel(const float* __restrict__ abf, const float* __restrict__ cbf,
                            const float* __restrict__ logstd) {
    const int t = threadIdx.x;
    if (t < An) {
        float s = 0.f;
        for (int m = 0; m < Mn; m++) s += abf[m * An + t];
        d_cst[t] = s;
    }
    if (t == 17) {
        float s = 0.f;
        for (int m = 0; m < Mn; m++) s += cbf[m];
        d_cst[19] = s;
    }
    if (t == 18) {
        float lp = 0.f, en = 0.f;
        for (int a = 0; a < An; a++) {
            lp += -logstd[a] - LOGS2PI;
            en += 0.5f + LOGS2PI + logstd[a];
        }
        d_cst[17] = lp;
        d_cst[18] = en;
    }
}

__global__ void pack_kernel(const float* __restrict__ actorOut, const float* __restrict__ val,
                            float* __restrict__ out) {
    const int gid = blockIdx.x * blockDim.x + threadIdx.x;
    const int b = gid / 20, k = gid % 20;
    float v;
    if (k < An)        v = actorOut[(size_t)b * An + k];
    else if (k == 17)  v = d_cst[17];
    else if (k == 18)  v = d_cst[18];
    else               v = val[b] + d_cst[19];
    out[gid] = v;
}

// ===================== host =====================
extern "C" void kernel_launch(void* const* d_in, const int* in_sizes, int n_in,
                              void* d_out, int out_size) {
    const float* x      = (const float*)d_in[0];
    const void*  tidx   = d_in[1];
    const float* W1     = (const float*)d_in[2];
    const float* b1     = (const float*)d_in[3];
    const float* W2     = (const float*)d_in[4];
    const float* b2     = (const float*)d_in[5];
    const float* emb    = (const float*)d_in[6];
    const float* a_rW   = (const float*)d_in[7];
    const float* a_rb   = (const float*)d_in[8];
    const float* c_rW   = (const float*)d_in[9];
    const float* c_rb   = (const float*)d_in[10];
    const float* a_W    = (const float*)d_in[11];
    const float* a_b    = (const float*)d_in[12];
    const float* a_Wf   = (const float*)d_in[13];
    const float* a_bf   = (const float*)d_in[14];
    const float* c_W    = (const float*)d_in[15];
    const float* c_b    = (const float*)d_in[16];
    const float* c_Wf   = (const float*)d_in[17];
    const float* c_bf   = (const float*)d_in[18];
    const float* logstd = (const float*)d_in[19];
    float* out = (float*)d_out;

    float *h1, *fs, *rel, *pA, *pC, *outs, *g0, *g1, *g2, *actorOut, *val, *cst;
    __nv_bfloat16 *we1, *we2, *war, *wcr, *wa, *wc, *waf;
    cudaGetSymbolAddress((void**)&h1, d_h1);
    cudaGetSymbolAddress((void**)&fs, d_fs);
    cudaGetSymbolAddress((void**)&rel, d_rel);
    cudaGetSymbolAddress((void**)&pA, d_probsA);
    cudaGetSymbolAddress((void**)&pC, d_probsC);
    cudaGetSymbolAddress((void**)&outs, d_outs);
    cudaGetSymbolAddress((void**)&g0, d_g0);
    cudaGetSymbolAddress((void**)&g1, d_g1);
    cudaGetSymbolAddress((void**)&g2, d_g2);
    cudaGetSymbolAddress((void**)&actorOut, d_actorOut);
    cudaGetSymbolAddress((void**)&val, d_val);
    cudaGetSymbolAddress((void**)&cst, d_cst);
    cudaGetSymbolAddress((void**)&we1, wt_e1);
    cudaGetSymbolAddress((void**)&we2, wt_e2);
    cudaGetSymbolAddress((void**)&war, wt_ar);
    cudaGetSymbolAddress((void**)&wcr, wt_cr);
    cudaGetSymbolAddress((void**)&wa, wt_a);
    cudaGetSymbolAddress((void**)&wc, wt_c);
    cudaGetSymbolAddress((void**)&waf, wt_af);

    // dynamic smem: 2 * (32768 + 2*NT*128)
    const int SM128 = 2 * (32768 + 2 * 128 * 128);  // 131072
    const int SM64  = 2 * (32768 + 2 * 64 * 128);   //  98304
    cudaFuncSetAttribute(mmagemm<128, 2, 1>, cudaFuncAttributeMaxDynamicSharedMemorySize, SM128);
    cudaFuncSetAttribute(mmagemm<128, 2, 2>, cudaFuncAttributeMaxDynamicSharedMemorySize, SM128);
    cudaFuncSetAttribute(mmagemm<64, 4, 0>,  cudaFuncAttributeMaxDynamicSharedMemorySize, SM64);

    detect_kernel<<<1, 256>>>((const int*)tidx);

    // weight conversion (transpose + bf16 hi/lo split)
    tconv_kernel<<<dim3(12, 16, 1),  dim3(32, 8)>>>(W1,   we1, OBSn, Hn, 384);
    tconv_kernel<<<dim3(16, 16, 1),  dim3(32, 8)>>>(W2,   we2, Hn,   Hn, 512);
    tconv_kernel<<<dim3(16, 2, 3),   dim3(32, 8)>>>(a_rW, war, Hn,   64, 512);
    tconv_kernel<<<dim3(16, 2, 3),   dim3(32, 8)>>>(c_rW, wcr, Hn,   64, 512);
    tconv_kernel<<<dim3(16, 16, 24), dim3(32, 8)>>>(a_W,  wa,  Hn,   Hn, 512);
    tconv_kernel<<<dim3(16, 16, 24), dim3(32, 8)>>>(c_W,  wc,  Hn,   Hn, 512);
    tconv_kernel<<<dim3(128, 2, 1),  dim3(32, 8)>>>(a_Wf, waf, Mn * Hn, An, 4096);

    // encoder
    mmagemm<128, 2, 2><<<dim3(128, 4, 1), 256, SM128>>>(x, OBSn, 0, we1, 384, 0, b1, 0,
                                                        h1, Hn, 0, Hn, OBSn);
    mmagemm<128, 2, 2><<<dim3(128, 4, 1), 256, SM128>>>(h1, Hn, 0, we2, 512, 0, b2, 0,
                                                        fs, Hn, 0, Hn, Hn);
    rel_kernel<<<(Bn * 128) / 256, 256>>>(fs, tidx, emb, rel);

    // routing (3 layers batched per net via grid z)
    mmagemm<64, 4, 0><<<dim3(128, 1, 3), 256, SM64>>>(rel, Hn, 0, war, 512, 64 * 1024,
                                                      a_rb, 64, pA, L1n * 64, 64, 64, Hn);
    mmagemm<64, 4, 0><<<dim3(128, 1, 3), 256, SM64>>>(rel, Hn, 0, wcr, 512, 64 * 1024,
                                                      c_rb, 64, pC, L1n * 64, 64, 64, Hn);
    softmax_kernel<<<(2 * Bn * L1n * 8) / 256, 256>>>(pA, pC);

    // critic chain: fs -> g0 -> g1 -> g2
    {
        const float* gprev = fs;
        float* gs[3] = {g0, g1, g2};
        for (int l = 0; l < L1n; l++) {
            mmagemm<128, 2, 1><<<dim3(128, 4, 8), 256, SM128>>>(
                (l == 0) ? fs : gprev, (l == 0) ? Hn : (Mn * Hn), (l == 0) ? 0 : Hn,
                wc + (size_t)l * Mn * 512 * 1024, 512, 512 * 1024,
                c_b + (size_t)l * Mn * Hn, Hn,
                outs, Mn * Hn, Hn, Hn, Hn);
            mix_kernel<<<Bn, 128>>>(pC + (size_t)l * 64, outs, gs[l]);
            gprev = gs[l];
        }
    }
    // actor chain: fs -> g0 -> g1 -> g0
    {
        const float* gprev = fs;
        float* gs[3] = {g0, g1, g0};
        for (int l = 0; l < L1n; l++) {
            mmagemm<128, 2, 1><<<dim3(128, 4, 8), 256, SM128>>>(
                (l == 0) ? fs : gprev, (l == 0) ? Hn : (Mn * Hn), (l == 0) ? 0 : Hn,
                wa + (size_t)l * Mn * 512 * 1024, 512, 512 * 1024,
                a_b + (size_t)l * Mn * Hn, Hn,
                outs, Mn * Hn, Hn, Hn, Hn);
            mix_kernel<<<Bn, 128>>>(pA + (size_t)l * 64, outs, gs[l]);
            gprev = gs[l];
        }
    }

    prep_kernel<<<1, 32>>>(a_bf, c_bf, logstd);
    // actor final: [B, 4096] @ [4096, 17] + summed bias
    mmagemm<64, 4, 0><<<dim3(128, 1, 1), 256, SM64>>>(g0, Mn * Hn, 0, waf, 4096, 0,
                                                      cst, 0, actorOut, An, 0, An, Mn * Hn);
    critic_kernel<<<Bn / 8, 256>>>(g2, c_Wf, val);
    pack_kernel<<<(Bn * 20) / 256, 256>>>(actorOut, val, out);
}

// round 5
// speedup vs baseline: 3.4774x; 1.0424x over previous
#include <cuda_runtime.h>
#include <cuda_bf16.h>
#include <math.h>
#include <stdint.h>

#define Bn   16384
#define OBSn 376
#define Hn   512
#define Mn   8
#define L1n  3
#define Tn   50
#define An   17
#define LOGS2PI 0.9189385332046727f

// ===================== helpers =====================
__device__ __forceinline__ uint32_t smem_to_u32(const void* p) {
    uint32_t a;
    asm("{ .reg .u64 t; cvta.to.shared.u64 t, %1; cvt.u32.u64 %0, t; }" : "=r"(a) : "l"(p));
    return a;
}
#define LDSM4(r0, r1, r2, r3, addr) \
    asm volatile("ldmatrix.sync.aligned.m8n8.x4.shared.b16 {%0,%1,%2,%3}, [%4];" \
        : "=r"(r0), "=r"(r1), "=r"(r2), "=r"(r3) : "r"(addr))
#define MMA16816(d, a, b0v, b1v) \
    asm volatile("mma.sync.aligned.m16n8k16.row.col.f32.bf16.bf16.f32 " \
        "{%0,%1,%2,%3}, {%4,%5,%6,%7}, {%8,%9}, {%0,%1,%2,%3};" \
        : "+f"((d)[0]), "+f"((d)[1]), "+f"((d)[2]), "+f"((d)[3]) \
        : "r"((a)[0]), "r"((a)[1]), "r"((a)[2]), "r"((a)[3]), "r"(b0v), "r"(b1v))
#define CP_ASYNC16(dst, src) \
    asm volatile("cp.async.cg.shared.global [%0], [%1], 16;" :: "r"(dst), "l"(src) : "memory")
#define CP_COMMIT() asm volatile("cp.async.commit_group;" ::: "memory")
template<int N> __device__ __forceinline__ void cp_wait() {
    asm volatile("cp.async.wait_group %0;" :: "n"(N) : "memory");
}

__device__ __forceinline__ uint32_t pack2bf(float a, float b) {
    __nv_bfloat162 p = __floats2bfloat162_rn(a, b);
    return *reinterpret_cast<uint32_t*>(&p);
}
__device__ __forceinline__ float residf(float v) {
    return v - __bfloat162float(__float2bfloat16(v));
}
__device__ __forceinline__ float2 bf2f2(uint32_t u) {
    __nv_bfloat162 h = *reinterpret_cast<__nv_bfloat162*>(&u);
    return __bfloat1622float2(h);
}

// ===================== scratch =====================
__device__ float d_probsA[(size_t)Bn * L1n * 64];
__device__ float d_probsC[(size_t)Bn * L1n * 64];
__device__ float d_actorOut[(size_t)Bn * An];
__device__ float d_val[Bn];
__device__ float d_cst[32];
__device__ int   d_is64;

// activation planes (bf16 hi/lo)
__device__ __align__(16) __nv_bfloat16 p_xhi[(size_t)Bn * 384];
__device__ __align__(16) __nv_bfloat16 p_xlo[(size_t)Bn * 384];
__device__ __align__(16) __nv_bfloat16 p_h1hi[(size_t)Bn * 512];
__device__ __align__(16) __nv_bfloat16 p_h1lo[(size_t)Bn * 512];
__device__ __align__(16) __nv_bfloat16 p_fshi[(size_t)Bn * 512];
__device__ __align__(16) __nv_bfloat16 p_fslo[(size_t)Bn * 512];
__device__ __align__(16) __nv_bfloat16 p_relhi[(size_t)Bn * 512];
__device__ __align__(16) __nv_bfloat16 p_rello[(size_t)Bn * 512];
__device__ __align__(16) __nv_bfloat16 p_outhi[(size_t)Bn * 4096];
__device__ __align__(16) __nv_bfloat16 p_outlo[(size_t)Bn * 4096];
__device__ __align__(16) __nv_bfloat16 p_g0hi[(size_t)Bn * 4096];
__device__ __align__(16) __nv_bfloat16 p_g0lo[(size_t)Bn * 4096];
__device__ __align__(16) __nv_bfloat16 p_g1hi[(size_t)Bn * 4096];
__device__ __align__(16) __nv_bfloat16 p_g1lo[(size_t)Bn * 4096];
__device__ __align__(16) __nv_bfloat16 p_g2hi[(size_t)Bn * 4096];
__device__ __align__(16) __nv_bfloat16 p_g2lo[(size_t)Bn * 4096];

// transposed/split weights: [slab][Nalloc][2*Kpad] bf16 (hi | lo)
__device__ __align__(16) __nv_bfloat16 wt_e1[(size_t)512 * 768];
__device__ __align__(16) __nv_bfloat16 wt_e2[(size_t)512 * 1024];
__device__ __align__(16) __nv_bfloat16 wt_ar[(size_t)3 * 64 * 1024];
__device__ __align__(16) __nv_bfloat16 wt_cr[(size_t)3 * 64 * 1024];
__device__ __align__(16) __nv_bfloat16 wt_a[(size_t)24 * 512 * 1024];
__device__ __align__(16) __nv_bfloat16 wt_c[(size_t)24 * 512 * 1024];
__device__ __align__(16) __nv_bfloat16 wt_af[(size_t)64 * 8192];

// ===================== task_idx dtype detector =====================
__global__ void detect_kernel(const int* __restrict__ ti) {
    __shared__ int ok;
    if (threadIdx.x == 0) ok = 1;
    __syncthreads();
    for (int i = threadIdx.x; i < 1024; i += blockDim.x) {
        int v = ti[i];
        bool good = (i & 1) ? (v == 0) : (v >= 0 && v < Tn);
        if (!good) atomicAnd(&ok, 0);
    }
    __syncthreads();
    if (threadIdx.x == 0) d_is64 = ok;
}

// ===================== x -> planes (pad 376 -> 384) =====================
__global__ void splitx_kernel(const float* __restrict__ x,
                              __nv_bfloat16* __restrict__ xhi, __nv_bfloat16* __restrict__ xlo) {
    const int gid = blockIdx.x * blockDim.x + threadIdx.x;  // Bn*96
    const int b = gid / 96, c4 = (gid % 96) * 4;
    float v[4];
#pragma unroll
    for (int e = 0; e < 4; ++e) {
        const int c = c4 + e;
        v[e] = (c < OBSn) ? x[(size_t)b * OBSn + c] : 0.f;
    }
    uint2 hi, lo;
    hi.x = pack2bf(v[0], v[1]); hi.y = pack2bf(v[2], v[3]);
    lo.x = pack2bf(residf(v[0]), residf(v[1])); lo.y = pack2bf(residf(v[2]), residf(v[3]));
    *(uint2*)(xhi + (size_t)b * 384 + c4) = hi;
    *(uint2*)(xlo + (size_t)b * 384 + c4) = lo;
}

// ===================== weight transpose + split =====================
__global__ void tconv_kernel(const float* __restrict__ W, __nv_bfloat16* __restrict__ Wt,
                             int K, int Nsrc, int Kpad) {
    __shared__ float t[32][33];
    const int Nalloc = gridDim.y * 32;
    W  += (size_t)blockIdx.z * K * Nsrc;
    Wt += (size_t)blockIdx.z * Nalloc * 2 * Kpad;
    const int k0 = blockIdx.x * 32, n0 = blockIdx.y * 32;
    for (int i = threadIdx.y; i < 32; i += 8) {
        int k = k0 + i, n = n0 + threadIdx.x;
        t[i][threadIdx.x] = (k < K && n < Nsrc) ? W[(size_t)k * Nsrc + n] : 0.f;
    }
    __syncthreads();
    for (int i = threadIdx.y; i < 32; i += 8) {
        int n = n0 + i, k = k0 + threadIdx.x;
        if (k < Kpad) {
            float v = t[threadIdx.x][i];
            __nv_bfloat16 hi = __float2bfloat16(v);
            __nv_bfloat16 lo = __float2bfloat16(v - __bfloat162float(hi));
            size_t base = (size_t)n * 2 * Kpad;
            Wt[base + k] = hi;
            Wt[base + Kpad + k] = lo;
        }
    }
}

// ===================== mma.sync split-bf16 GEMM, all-cp.async, 3 stages =====================
// A and B both preconverted bf16 hi/lo planes. CTA 128 x NT, 8 warps, K chunk 64.
// Stage smem: A_hi(16K) | A_lo(16K) | B_hi(NT*128) | B_lo(NT*128).
// EPI: 0 = fp32 C, 1 = hi/lo planes out.
template<int NT, int WARPS_M, int ACT, int EPI>
__global__ __launch_bounds__(256, 1) void mmagemm(
    const __nv_bfloat16* __restrict__ Ahi, const __nv_bfloat16* __restrict__ Alo,
    int lda, long long a_off,
    const __nv_bfloat16* __restrict__ Wt, int Kpad, long long w_bs,
    const float* __restrict__ bias, int b_bs,
    float* __restrict__ C, __nv_bfloat16* __restrict__ Chi, __nv_bfloat16* __restrict__ Clo,
    int ldc, long long c_off,
    int N_STORE, int NC)
{
    extern __shared__ char smem[];
    const uint32_t sb = smem_to_u32(smem);
    const int tid = threadIdx.x, wid = tid >> 5, lane = tid & 31;
    const int m0 = blockIdx.x * 128;
    const int n0g = blockIdx.y * NT;
    const int zb = blockIdx.z;
    Ahi  += (size_t)zb * a_off;
    Alo  += (size_t)zb * a_off;
    Wt   += (size_t)zb * w_bs + (size_t)n0g * (2 * Kpad);
    bias += (size_t)zb * b_bs + n0g;

    constexpr int MT = 128 / (16 * WARPS_M);
    constexpr int BB = NT * 128;
    constexpr int STAGE = 32768 + 2 * BB;
    const int wm0 = (wid % WARPS_M) * (MT * 16);
    const int wn0 = (wid / WARPS_M) * 32;

    float acc[MT][4][4];
#pragma unroll
    for (int mt = 0; mt < MT; ++mt)
#pragma unroll
        for (int nt = 0; nt < 4; ++nt)
#pragma unroll
            for (int e = 0; e < 4; ++e) acc[mt][nt][e] = 0.f;

    auto issue = [&](int c, int buf) {
        const int k0 = c << 6;
        const uint32_t dbase = sb + buf * STAGE;
        // A: 128 rows x 64k, hi+lo planes
#pragma unroll
        for (int it = 0; it < 4; ++it) {
            const int seg = it * 256 + tid;
            const int r = seg >> 3;
            const int ksb = (seg & 7) * 16;
            const int kelt = k0 + (seg & 7) * 8;
            const uint32_t doff = (uint32_t)r * 128 + ((uint32_t)ksb ^ (((uint32_t)r & 7) << 4));
            const size_t aoff = (size_t)(m0 + r) * lda + kelt;
            CP_ASYNC16(dbase + doff, Ahi + aoff);
            CP_ASYNC16(dbase + 16384 + doff, Alo + aoff);
        }
        // B: NT rows x 64k, hi+lo regions
#pragma unroll
        for (int it = 0; it < NT / 32; ++it) {
            const int seg = it * 256 + tid;
            const int r = seg >> 3;
            const int ksb = (seg & 7) * 16;
            const int kelt = k0 + (seg & 7) * 8;
            const uint32_t doff = (uint32_t)r * 128 + ((uint32_t)ksb ^ (((uint32_t)r & 7) << 4));
            const __nv_bfloat16* src = Wt + (size_t)r * (2 * Kpad) + kelt;
            CP_ASYNC16(dbase + 32768 + doff, src);
            CP_ASYNC16(dbase + 32768 + BB + doff, src + Kpad);
        }
        CP_COMMIT();
    };

    auto compute = [&](int buf) {
        const uint32_t ab  = sb + buf * STAGE;
        const uint32_t alb = ab + 16384;
        const uint32_t bb  = ab + 32768;
        const uint32_t blb = bb + BB;
        const uint32_t xm = ((uint32_t)lane & 7) << 4;
        const int ra = ((lane >> 3) & 1) * 8 + (lane & 7);
        const int ka = ((lane >> 4) & 1) * 16;
        const int rb = ((lane >> 4) & 1) * 8 + (lane & 7);
        const int kb = ((lane >> 3) & 1) * 16;
#pragma unroll
        for (int s = 0; s < 4; ++s) {
            const int ksb = s * 32;
            uint32_t Ah[MT][4], Al[MT][4], Bh[4][2], Bl[4][2];
#pragma unroll
            for (int mt = 0; mt < MT; ++mt) {
                const uint32_t off = (uint32_t)(wm0 + mt * 16 + ra) * 128 +
                                     (((uint32_t)(ksb + ka)) ^ xm);
                LDSM4(Ah[mt][0], Ah[mt][1], Ah[mt][2], Ah[mt][3], ab + off);
                LDSM4(Al[mt][0], Al[mt][1], Al[mt][2], Al[mt][3], alb + off);
            }
#pragma unroll
            for (int p = 0; p < 2; ++p) {
                const uint32_t off = (uint32_t)(wn0 + p * 16 + rb) * 128 +
                                     (((uint32_t)(ksb + kb)) ^ xm);
                LDSM4(Bh[2 * p][0], Bh[2 * p][1], Bh[2 * p + 1][0], Bh[2 * p + 1][1], bb + off);
                LDSM4(Bl[2 * p][0], Bl[2 * p][1], Bl[2 * p + 1][0], Bl[2 * p + 1][1], blb + off);
            }
#pragma unroll
            for (int mt = 0; mt < MT; ++mt)
#pragma unroll
                for (int nt = 0; nt < 4; ++nt)
                    MMA16816(acc[mt][nt], Ah[mt], Bh[nt][0], Bh[nt][1]);
#pragma unroll
            for (int mt = 0; mt < MT; ++mt)
#pragma unroll
                for (int nt = 0; nt < 4; ++nt)
                    MMA16816(acc[mt][nt], Al[mt], Bh[nt][0], Bh[nt][1]);
#pragma unroll
            for (int mt = 0; mt < MT; ++mt)
#pragma unroll
                for (int nt = 0; nt < 4; ++nt)
                    MMA16816(acc[mt][nt], Ah[mt], Bl[nt][0], Bl[nt][1]);
        }
    };

    // 3-stage pipeline, one group committed per iteration (empty commits keep accounting exact)
    issue(0, 0);
    issue(1, 1);
    for (int c = 0; c < NC; ++c) {
        cp_wait<1>();
        __syncthreads();
        if (c + 2 < NC) issue(c + 2, (c + 2) % 3);
        else CP_COMMIT();
        compute(c % 3);
    }

    // epilogue
    const int g = lane >> 2, t = lane & 3;
#pragma unroll
    for (int mt = 0; mt < MT; ++mt) {
#pragma unroll
        for (int nt = 0; nt < 4; ++nt) {
            const int col = wn0 + nt * 8 + t * 2;
            float v0 = acc[mt][nt][0], v1 = acc[mt][nt][1];
            float v2 = acc[mt][nt][2], v3 = acc[mt][nt][3];
            const int row0 = m0 + wm0 + mt * 16 + g;
            if (EPI == 1) {
                const float bv0 = bias[col], bv1 = bias[col + 1];
                v0 += bv0; v1 += bv1; v2 += bv0; v3 += bv1;
                if (ACT == 1) { v0 = fmaxf(v0, 0.f); v1 = fmaxf(v1, 0.f); v2 = fmaxf(v2, 0.f); v3 = fmaxf(v3, 0.f); }
                if (ACT == 2) { v0 = tanhf(v0); v1 = tanhf(v1); v2 = tanhf(v2); v3 = tanhf(v3); }
                const size_t o0 = (size_t)zb * c_off + (size_t)row0 * ldc + n0g + col;
                const size_t o1 = (size_t)zb * c_off + (size_t)(row0 + 8) * ldc + n0g + col;
                *(uint32_t*)(Chi + o0) = pack2bf(v0, v1);
                *(uint32_t*)(Clo + o0) = pack2bf(residf(v0), residf(v1));
                *(uint32_t*)(Chi + o1) = pack2bf(v2, v3);
                *(uint32_t*)(Clo + o1) = pack2bf(residf(v2), residf(v3));
            } else {
                const int rem = N_STORE - n0g;
                const float bv0 = (col < rem) ? bias[col] : 0.f;
                const float bv1 = (col + 1 < rem) ? bias[col + 1] : 0.f;
                v0 += bv0; v1 += bv1; v2 += bv0; v3 += bv1;
                if (ACT == 1) { v0 = fmaxf(v0, 0.f); v1 = fmaxf(v1, 0.f); v2 = fmaxf(v2, 0.f); v3 = fmaxf(v3, 0.f); }
                if (ACT == 2) { v0 = tanhf(v0); v1 = tanhf(v1); v2 = tanhf(v2); v3 = tanhf(v3); }
                float* Cb = C + (size_t)zb * c_off + n0g;
                if (col < rem) {
                    Cb[(size_t)row0 * ldc + col] = v0;
                    Cb[(size_t)(row0 + 8) * ldc + col] = v2;
                }
                if (col + 1 < rem) {
                    Cb[(size_t)row0 * ldc + col + 1] = v1;
                    Cb[(size_t)(row0 + 8) * ldc + col + 1] = v3;
                }
            }
        }
    }
}

// ===================== rel = relu(fs * emb[idx]) -> planes =====================
__global__ void rel_kernel(const __nv_bfloat16* __restrict__ fshi, const __nv_bfloat16* __restrict__ fslo,
                           const void* __restrict__ tidx, const float* __restrict__ emb,
                           __nv_bfloat16* __restrict__ rhi, __nv_bfloat16* __restrict__ rlo) {
    const int gid = blockIdx.x * blockDim.x + threadIdx.x;
    const int b = gid >> 7, h4 = (gid & 127) * 4;
    long long ti;
    if (d_is64) ti = ((const long long*)tidx)[b];
    else        ti = (long long)((const int*)tidx)[b];
    const size_t base = (size_t)b * Hn + h4;
    uint2 hu = *(const uint2*)(fshi + base);
    uint2 lu = *(const uint2*)(fslo + base);
    float2 h0 = bf2f2(hu.x), h1 = bf2f2(hu.y), l0 = bf2f2(lu.x), l1 = bf2f2(lu.y);
    float4 e = *(const float4*)(emb + (size_t)ti * Hn + h4);
    float r0 = fmaxf((h0.x + l0.x) * e.x, 0.f);
    float r1 = fmaxf((h0.y + l0.y) * e.y, 0.f);
    float r2 = fmaxf((h1.x + l1.x) * e.z, 0.f);
    float r3 = fmaxf((h1.y + l1.y) * e.w, 0.f);
    uint2 oh, ol;
    oh.x = pack2bf(r0, r1); oh.y = pack2bf(r2, r3);
    ol.x = pack2bf(residf(r0), residf(r1)); ol.y = pack2bf(residf(r2), residf(r3));
    *(uint2*)(rhi + base) = oh;
    *(uint2*)(rlo + base) = ol;
}

// ===================== softmax over groups of 8 =====================
__global__ void softmax_kernel(float* __restrict__ pA, float* __restrict__ pC) {
    const int gid = blockIdx.x * blockDim.x + threadIdx.x;
    const int per = Bn * L1n * 8;
    float* p = (gid < per) ? (pA + (size_t)gid * 8) : (pC + (size_t)(gid - per) * 8);
    float v[8], mx = -1e30f;
#pragma unroll
    for (int j = 0; j < 8; j++) { v[j] = p[j]; mx = fmaxf(mx, v[j]); }
    float s = 0.f;
#pragma unroll
    for (int j = 0; j < 8; j++) { v[j] = __expf(v[j] - mx); s += v[j]; }
    const float inv = 1.f / s;
#pragma unroll
    for (int j = 0; j < 8; j++) p[j] = v[j] * inv;
}

// ===================== mix (planes in, planes out) =====================
__global__ void mix_kernel(const float* __restrict__ probs,
                           const __nv_bfloat16* __restrict__ ohi, const __nv_bfloat16* __restrict__ olo,
                           __nv_bfloat16* __restrict__ ghi, __nv_bfloat16* __restrict__ glo) {
    __shared__ float p[64];
    const int b = blockIdx.x, tid = threadIdx.x;
    if (tid < 64) p[tid] = probs[(size_t)b * (L1n * 64) + tid];
    __syncthreads();
    const size_t base = (size_t)b * 4096 + tid * 4;
    float o[8][4];
#pragma unroll
    for (int j = 0; j < 8; j++) {
        uint2 hu = *(const uint2*)(ohi + base + j * 512);
        uint2 lu = *(const uint2*)(olo + base + j * 512);
        float2 h0 = bf2f2(hu.x), h1 = bf2f2(hu.y), l0 = bf2f2(lu.x), l1 = bf2f2(lu.y);
        o[j][0] = h0.x + l0.x; o[j][1] = h0.y + l0.y;
        o[j][2] = h1.x + l1.x; o[j][3] = h1.y + l1.y;
    }
#pragma unroll
    for (int i = 0; i < 8; i++) {
        float a0 = 0.f, a1 = 0.f, a2 = 0.f, a3 = 0.f;
#pragma unroll
        for (int j = 0; j < 8; j++) {
            const float w = p[i * 8 + j];
            a0 = fmaf(w, o[j][0], a0);
            a1 = fmaf(w, o[j][1], a1);
            a2 = fmaf(w, o[j][2], a2);
            a3 = fmaf(w, o[j][3], a3);
        }
        uint2 oh, ol;
        oh.x = pack2bf(a0, a1); oh.y = pack2bf(a2, a3);
        ol.x = pack2bf(residf(a0), residf(a1)); ol.y = pack2bf(residf(a2), residf(a3));
        *(uint2*)(ghi + base + i * 512) = oh;
        *(uint2*)(glo + base + i * 512) = ol;
    }
}

// ===================== critic final (planes) =====================
__global__ void critic_kernel(const __nv_bfloat16* __restrict__ ghi, const __nv_bfloat16* __restrict__ glo,
                              const float* __restrict__ wf, float* __restrict__ val) {
    const int w = (blockIdx.x * blockDim.x + threadIdx.x) >> 5;
    const int lane = threadIdx.x & 31;
    const size_t off = (size_t)w * (Mn * Hn);
    float s = 0.f;
    for (int i = lane * 2; i < Mn * Hn; i += 64) {
        float2 h = bf2f2(*(const uint32_t*)(ghi + off + i));
        float2 l = bf2f2(*(const uint32_t*)(glo + off + i));
        float2 f = *(const float2*)(wf + i);
        s = fmaf(h.x + l.x, f.x, s);
        s = fmaf(h.y + l.y, f.y, s);
    }
#pragma unroll
    for (int o = 16; o > 0; o >>= 1) s += __shfl_xor_sync(0xFFFFFFFFu, s, o);
    if (lane == 0) val[w] = s;
}

__global__ void prep_kernel(const float* __restrict__ abf, const float* __restrict__ cbf,
                            const float* __restrict__ logstd) {
    const int t = threadIdx.x;
    if (t < An) {
        float s = 0.f;
        for (int m = 0; m < Mn; m++) s += abf[m * An + t];
        d_cst[t] = s;
    }
    if (t == 17) {
        float s = 0.f;
        for (int m = 0; m < Mn; m++) s += cbf[m];
        d_cst[19] = s;
    }
    if (t == 18) {
        float lp = 0.f, en = 0.f;
        for (int a = 0; a < An; a++) {
            lp += -logstd[a] - LOGS2PI;
            en += 0.5f + LOGS2PI + logstd[a];
        }
        d_cst[17] = lp;
        d_cst[18] = en;
    }
}

__global__ void pack_kernel(const float* __restrict__ actorOut, const float* __restrict__ val,
                            float* __restrict__ out) {
    const int gid = blockIdx.x * blockDim.x + threadIdx.x;
    const int b = gid / 20, k = gid % 20;
    float v;
    if (k < An)        v = actorOut[(size_t)b * An + k];
    else if (k == 17)  v = d_cst[17];
    else if (k == 18)  v = d_cst[18];
    else               v = val[b] + d_cst[19];
    out[gid] = v;
}

// ===================== host =====================
extern "C" void kernel_launch(void* const* d_in, const int* in_sizes, int n_in,
                              void* d_out, int out_size) {
    const float* x      = (const float*)d_in[0];
    const void*  tidx   = d_in[1];
    const float* W1     = (const float*)d_in[2];
    const float* b1     = (const float*)d_in[3];
    const float* W2     = (const float*)d_in[4];
    const float* b2     = (const float*)d_in[5];
    const float* emb    = (const float*)d_in[6];
    const float* a_rW   = (const float*)d_in[7];
    const float* a_rb   = (const float*)d_in[8];
    const float* c_rW   = (const float*)d_in[9];
    const float* c_rb   = (const float*)d_in[10];
    const float* a_W    = (const float*)d_in[11];
    const float* a_b    = (const float*)d_in[12];
    const float* a_Wf   = (const float*)d_in[13];
    const float* a_bf   = (const float*)d_in[14];
    const float* c_W    = (const float*)d_in[15];
    const float* c_b    = (const float*)d_in[16];
    const float* c_Wf   = (const float*)d_in[17];
    const float* c_bf   = (const float*)d_in[18];
    const float* logstd = (const float*)d_in[19];
    float* out = (float*)d_out;

    float *pA, *pC, *actorOut, *val, *cst;
    __nv_bfloat16 *xhi, *xlo, *h1hi, *h1lo, *fshi, *fslo, *rhi, *rlo;
    __nv_bfloat16 *ohi, *olo, *g0hi, *g0lo, *g1hi, *g1lo, *g2hi, *g2lo;
    __nv_bfloat16 *we1, *we2, *war, *wcr, *wa, *wc, *waf;
    cudaGetSymbolAddress((void**)&pA, d_probsA);
    cudaGetSymbolAddress((void**)&pC, d_probsC);
    cudaGetSymbolAddress((void**)&actorOut, d_actorOut);
    cudaGetSymbolAddress((void**)&val, d_val);
    cudaGetSymbolAddress((void**)&cst, d_cst);
    cudaGetSymbolAddress((void**)&xhi, p_xhi);
    cudaGetSymbolAddress((void**)&xlo, p_xlo);
    cudaGetSymbolAddress((void**)&h1hi, p_h1hi);
    cudaGetSymbolAddress((void**)&h1lo, p_h1lo);
    cudaGetSymbolAddress((void**)&fshi, p_fshi);
    cudaGetSymbolAddress((void**)&fslo, p_fslo);
    cudaGetSymbolAddress((void**)&rhi, p_relhi);
    cudaGetSymbolAddress((void**)&rlo, p_rello);
    cudaGetSymbolAddress((void**)&ohi, p_outhi);
    cudaGetSymbolAddress((void**)&olo, p_outlo);
    cudaGetSymbolAddress((void**)&g0hi, p_g0hi);
    cudaGetSymbolAddress((void**)&g0lo, p_g0lo);
    cudaGetSymbolAddress((void**)&g1hi, p_g1hi);
    cudaGetSymbolAddress((void**)&g1lo, p_g1lo);
    cudaGetSymbolAddress((void**)&g2hi, p_g2hi);
    cudaGetSymbolAddress((void**)&g2lo, p_g2lo);
    cudaGetSymbolAddress((void**)&we1, wt_e1);
    cudaGetSymbolAddress((void**)&we2, wt_e2);
    cudaGetSymbolAddress((void**)&war, wt_ar);
    cudaGetSymbolAddress((void**)&wcr, wt_cr);
    cudaGetSymbolAddress((void**)&wa, wt_a);
    cudaGetSymbolAddress((void**)&wc, wt_c);
    cudaGetSymbolAddress((void**)&waf, wt_af);

    // dynamic smem: 3 * (32768 + 2*NT*128)
    const int SM128 = 3 * (32768 + 2 * 128 * 128);  // 196608
    const int SM64  = 3 * (32768 + 2 * 64 * 128);   // 147456
    cudaFuncSetAttribute(mmagemm<128, 2, 1, 1>, cudaFuncAttributeMaxDynamicSharedMemorySize, SM128);
    cudaFuncSetAttribute(mmagemm<128, 2, 2, 1>, cudaFuncAttributeMaxDynamicSharedMemorySize, SM128);
    cudaFuncSetAttribute(mmagemm<64, 4, 0, 0>,  cudaFuncAttributeMaxDynamicSharedMemorySize, SM64);

    detect_kernel<<<1, 256>>>((const int*)tidx);
    splitx_kernel<<<(Bn * 96) / 256, 256>>>(x, xhi, xlo);

    // weight conversion (transpose + bf16 hi/lo split)
    tconv_kernel<<<dim3(12, 16, 1),  dim3(32, 8)>>>(W1,   we1, OBSn, Hn, 384);
    tconv_kernel<<<dim3(16, 16, 1),  dim3(32, 8)>>>(W2,   we2, Hn,   Hn, 512);
    tconv_kernel<<<dim3(16, 2, 3),   dim3(32, 8)>>>(a_rW, war, Hn,   64, 512);
    tconv_kernel<<<dim3(16, 2, 3),   dim3(32, 8)>>>(c_rW, wcr, Hn,   64, 512);
    tconv_kernel<<<dim3(16, 16, 24), dim3(32, 8)>>>(a_W,  wa,  Hn,   Hn, 512);
    tconv_kernel<<<dim3(16, 16, 24), dim3(32, 8)>>>(c_W,  wc,  Hn,   Hn, 512);
    tconv_kernel<<<dim3(128, 2, 1),  dim3(32, 8)>>>(a_Wf, waf, Mn * Hn, An, 4096);

    // encoder (planes in, planes out)
    mmagemm<128, 2, 2, 1><<<dim3(128, 4, 1), 256, SM128>>>(
        xhi, xlo, 384, 0, we1, 384, 0, b1, 0,
        nullptr, h1hi, h1lo, Hn, 0, Hn, 6);
    mmagemm<128, 2, 2, 1><<<dim3(128, 4, 1), 256, SM128>>>(
        h1hi, h1lo, Hn, 0, we2, 512, 0, b2, 0,
        nullptr, fshi, fslo, Hn, 0, Hn, 8);
    rel_kernel<<<(Bn * 128) / 256, 256>>>(fshi, fslo, tidx, emb, rhi, rlo);

    // routing (3 layers batched via grid z) -> fp32 probs
    mmagemm<64, 4, 0, 0><<<dim3(128, 1, 3), 256, SM64>>>(
        rhi, rlo, Hn, 0, war, 512, 64 * 1024, a_rb, 64,
        pA, nullptr, nullptr, L1n * 64, 64, 64, 8);
    mmagemm<64, 4, 0, 0><<<dim3(128, 1, 3), 256, SM64>>>(
        rhi, rlo, Hn, 0, wcr, 512, 64 * 1024, c_rb, 64,
        pC, nullptr, nullptr, L1n * 64, 64, 64, 8);
    softmax_kernel<<<(2 * Bn * L1n * 8) / 256, 256>>>(pA, pC);

    // critic chain: fs -> g0 -> g1 -> g2
    {
        const __nv_bfloat16* ghp = fshi;
        const __nv_bfloat16* glp = fslo;
        __nv_bfloat16* gsh[3] = {g0hi, g1hi, g2hi};
        __nv_bfloat16* gsl[3] = {g0lo, g1lo, g2lo};
        for (int l = 0; l < L1n; l++) {
            mmagemm<128, 2, 1, 1><<<dim3(128, 4, 8), 256, SM128>>>(
                ghp, glp, (l == 0) ? Hn : (Mn * Hn), (l == 0) ? 0 : Hn,
                wc + (size_t)l * Mn * 512 * 1024, 512, 512 * 1024,
                c_b + (size_t)l * Mn * Hn, Hn,
                nullptr, ohi, olo, Mn * Hn, Hn, Hn, 8);
            mix_kernel<<<Bn, 128>>>(pC + (size_t)l * 64, ohi, olo, gsh[l], gsl[l]);
            ghp = gsh[l]; glp = gsl[l];
        }
    }
    // actor chain: fs -> g0 -> g1 -> g0
    {
        const __nv_bfloat16* ghp = fshi;
        const __nv_bfloat16* glp = fslo;
        __nv_bfloat16* gsh[3] = {g0hi, g1hi, g0hi};
        __nv_bfloat16* gsl[3] = {g0lo, g1lo, g0lo};
        for (int l = 0; l < L1n; l++) {
            mmagemm<128, 2, 1, 1><<<dim3(128, 4, 8), 256, SM128>>>(
                ghp, glp, (l == 0) ? Hn : (Mn * Hn), (l == 0) ? 0 : Hn,
                wa + (size_t)l * Mn * 512 * 1024, 512, 512 * 1024,
                a_b + (size_t)l * Mn * Hn, Hn,
                nullptr, ohi, olo, Mn * Hn, Hn, Hn, 8);
            mix_kernel<<<Bn, 128>>>(pA + (size_t)l * 64, ohi, olo, gsh[l], gsl[l]);
            ghp = gsh[l]; glp = gsl[l];
        }
    }

    prep_kernel<<<1, 32>>>(a_bf, c_bf, logstd);
    // actor final: [B, 4096] @ [4096, 17] + summed bias
    mmagemm<64, 4, 0, 0><<<dim3(128, 1, 1), 256, SM64>>>(
        g0hi, g0lo, Mn * Hn, 0, waf, 4096, 0, cst, 0,
        actorOut, nullptr, nullptr, An, 0, An, 64);
    critic_kernel<<<Bn / 8, 256>>>(g2hi, g2lo, c_Wf, val);
    pack_kernel<<<(Bn * 20) / 256, 256>>>(actorOut, val, out);
}

// round 6
// speedup vs baseline: 5.9895x; 1.7224x over previous
#include <cuda_runtime.h>
#include <cuda_fp16.h>
#include <math.h>
#include <stdint.h>

#define Bn   16384
#define OBSn 376
#define Hn   512
#define Mn   8
#define L1n  3
#define Tn   50
#define An   17
#define LOGS2PI 0.9189385332046727f

// ===================== helpers =====================
__device__ __forceinline__ uint32_t smem_to_u32(const void* p) {
    uint32_t a;
    asm("{ .reg .u64 t; cvta.to.shared.u64 t, %1; cvt.u32.u64 %0, t; }" : "=r"(a) : "l"(p));
    return a;
}
#define LDSM4(r0, r1, r2, r3, addr) \
    asm volatile("ldmatrix.sync.aligned.m8n8.x4.shared.b16 {%0,%1,%2,%3}, [%4];" \
        : "=r"(r0), "=r"(r1), "=r"(r2), "=r"(r3) : "r"(addr))
#define MMA16816(d, a, b0v, b1v) \
    asm volatile("mma.sync.aligned.m16n8k16.row.col.f32.f16.f16.f32 " \
        "{%0,%1,%2,%3}, {%4,%5,%6,%7}, {%8,%9}, {%0,%1,%2,%3};" \
        : "+f"((d)[0]), "+f"((d)[1]), "+f"((d)[2]), "+f"((d)[3]) \
        : "r"((a)[0]), "r"((a)[1]), "r"((a)[2]), "r"((a)[3]), "r"(b0v), "r"(b1v))
#define CP_ASYNC16(dst, src) \
    asm volatile("cp.async.cg.shared.global [%0], [%1], 16;" :: "r"(dst), "l"(src) : "memory")
#define CP_COMMIT() asm volatile("cp.async.commit_group;" ::: "memory")
template<int N> __device__ __forceinline__ void cp_wait() {
    asm volatile("cp.async.wait_group %0;" :: "n"(N) : "memory");
}

__device__ __forceinline__ uint32_t packh2(float a, float b) {
    __half2 h = __floats2half2_rn(a, b);
    return *reinterpret_cast<uint32_t*>(&h);
}
__device__ __forceinline__ float2 h2f2(uint32_t u) {
    __half2 h = *reinterpret_cast<__half2*>(&u);
    return __half22float2(h);
}

// ===================== scratch =====================
__device__ float d_probsA[(size_t)Bn * L1n * 64];
__device__ float d_probsC[(size_t)Bn * L1n * 64];
__device__ float d_actorOut[(size_t)Bn * An];
__device__ float d_val[Bn];
__device__ float d_cst[32];
__device__ int   d_is64;

// activation planes (single fp16)
__device__ __align__(16) __half p_x[(size_t)Bn * 384];
__device__ __align__(16) __half p_h1[(size_t)Bn * 512];
__device__ __align__(16) __half p_fs[(size_t)Bn * 512];
__device__ __align__(16) __half p_rel[(size_t)Bn * 512];
__device__ __align__(16) __half p_out[(size_t)Bn * 4096];
__device__ __align__(16) __half p_g0[(size_t)Bn * 4096];
__device__ __align__(16) __half p_g1[(size_t)Bn * 4096];
__device__ __align__(16) __half p_g2[(size_t)Bn * 4096];

// transposed/split weights: [slab][Nalloc][2*Kpad] fp16 (hi | lo)
__device__ __align__(16) __half wt_e1[(size_t)512 * 768];
__device__ __align__(16) __half wt_e2[(size_t)512 * 1024];
__device__ __align__(16) __half wt_ar[(size_t)3 * 64 * 1024];
__device__ __align__(16) __half wt_cr[(size_t)3 * 64 * 1024];
__device__ __align__(16) __half wt_a[(size_t)24 * 512 * 1024];
__device__ __align__(16) __half wt_c[(size_t)24 * 512 * 1024];
__device__ __align__(16) __half wt_af[(size_t)64 * 8192];

// ===================== task_idx dtype detector =====================
__global__ void detect_kernel(const int* __restrict__ ti) {
    __shared__ int ok;
    if (threadIdx.x == 0) ok = 1;
    __syncthreads();
    for (int i = threadIdx.x; i < 1024; i += blockDim.x) {
        int v = ti[i];
        bool good = (i & 1) ? (v == 0) : (v >= 0 && v < Tn);
        if (!good) atomicAnd(&ok, 0);
    }
    __syncthreads();
    if (threadIdx.x == 0) d_is64 = ok;
}

// ===================== x -> fp16 plane (pad 376 -> 384) =====================
__global__ void splitx_kernel(const float* __restrict__ x, __half* __restrict__ xp) {
    const int gid = blockIdx.x * blockDim.x + threadIdx.x;  // Bn*96
    const int b = gid / 96, c4 = (gid % 96) * 4;
    float v[4];
#pragma unroll
    for (int e = 0; e < 4; ++e) {
        const int c = c4 + e;
        v[e] = (c < OBSn) ? x[(size_t)b * OBSn + c] : 0.f;
    }
    uint2 o;
    o.x = packh2(v[0], v[1]);
    o.y = packh2(v[2], v[3]);
    *(uint2*)(xp + (size_t)b * 384 + c4) = o;
}

// ===================== weight transpose + fp16 hi/lo split =====================
__global__ void tconv_kernel(const float* __restrict__ W, __half* __restrict__ Wt,
                             int K, int Nsrc, int Kpad) {
    __shared__ float t[32][33];
    const int Nalloc = gridDim.y * 32;
    W  += (size_t)blockIdx.z * K * Nsrc;
    Wt += (size_t)blockIdx.z * Nalloc * 2 * Kpad;
    const int k0 = blockIdx.x * 32, n0 = blockIdx.y * 32;
    for (int i = threadIdx.y; i < 32; i += 8) {
        int k = k0 + i, n = n0 + threadIdx.x;
        t[i][threadIdx.x] = (k < K && n < Nsrc) ? W[(size_t)k * Nsrc + n] : 0.f;
    }
    __syncthreads();
    for (int i = threadIdx.y; i < 32; i += 8) {
        int n = n0 + i, k = k0 + threadIdx.x;
        if (k < Kpad) {
            float v = t[threadIdx.x][i];
            __half hi = __float2half_rn(v);
            __half lo = __float2half_rn(v - __half2float(hi));
            size_t base = (size_t)n * 2 * Kpad;
            Wt[base + k] = hi;
            Wt[base + Kpad + k] = lo;
        }
    }
}

// ===================== mma.sync 2-term fp16 GEMM (A single, B hi/lo) =====================
// C = act(A @ (Bh+Bl) + bias). CTA 128 x NT, 8 warps, K chunk 64, 2-stage, 2 CTAs/SM.
// Stage smem: A(16K) | B_hi(NT*128) | B_lo(NT*128).
template<int NT, int WARPS_M, int ACT, int EPI>  // EPI: 0 fp32 C, 1 fp16 plane
__global__ __launch_bounds__(256, 2) void mmagemm(
    const __half* __restrict__ A, int lda, long long a_off,
    const __half* __restrict__ Wt, int Kpad, long long w_bs,
    const float* __restrict__ bias, int b_bs,
    float* __restrict__ C, __half* __restrict__ Ch, int ldc, long long c_off,
    int N_STORE, int NC)
{
    extern __shared__ char smem[];
    const uint32_t sb = smem_to_u32(smem);
    const int tid = threadIdx.x, wid = tid >> 5, lane = tid & 31;
    const int m0 = blockIdx.x * 128;
    const int n0g = blockIdx.y * NT;
    const int zb = blockIdx.z;
    A    += (size_t)zb * a_off;
    Wt   += (size_t)zb * w_bs + (size_t)n0g * (2 * Kpad);
    bias += (size_t)zb * b_bs + n0g;

    constexpr int MT = 128 / (16 * WARPS_M);
    constexpr int BB = NT * 128;
    constexpr int STAGE = 16384 + 2 * BB;
    const int wm0 = (wid % WARPS_M) * (MT * 16);
    const int wn0 = (wid / WARPS_M) * 32;

    float acc[MT][4][4];
#pragma unroll
    for (int mt = 0; mt < MT; ++mt)
#pragma unroll
        for (int nt = 0; nt < 4; ++nt)
#pragma unroll
            for (int e = 0; e < 4; ++e) acc[mt][nt][e] = 0.f;

    auto issue = [&](int c, int buf) {
        const int k0 = c << 6;
        const uint32_t dbase = sb + buf * STAGE;
        // A: 128 rows x 64k fp16
#pragma unroll
        for (int it = 0; it < 4; ++it) {
            const int seg = it * 256 + tid;
            const int r = seg >> 3;
            const int ksb = (seg & 7) * 16;
            const int kelt = k0 + (seg & 7) * 8;
            const uint32_t doff = (uint32_t)r * 128 + ((uint32_t)ksb ^ (((uint32_t)r & 7) << 4));
            CP_ASYNC16(dbase + doff, A + (size_t)(m0 + r) * lda + kelt);
        }
        // B: NT rows x 64k, hi + lo
#pragma unroll
        for (int it = 0; it < NT / 32; ++it) {
            const int seg = it * 256 + tid;
            const int r = seg >> 3;
            const int ksb = (seg & 7) * 16;
            const int kelt = k0 + (seg & 7) * 8;
            const uint32_t doff = (uint32_t)r * 128 + ((uint32_t)ksb ^ (((uint32_t)r & 7) << 4));
            const __half* src = Wt + (size_t)r * (2 * Kpad) + kelt;
            CP_ASYNC16(dbase + 16384 + doff, src);
            CP_ASYNC16(dbase + 16384 + BB + doff, src + Kpad);
        }
        CP_COMMIT();
    };

    auto compute = [&](int buf) {
        const uint32_t ab  = sb + buf * STAGE;
        const uint32_t bb  = ab + 16384;
        const uint32_t blb = bb + BB;
        const uint32_t xm = ((uint32_t)lane & 7) << 4;
        const int ra = ((lane >> 3) & 1) * 8 + (lane & 7);
        const int ka = ((lane >> 4) & 1) * 16;
        const int rb = ((lane >> 4) & 1) * 8 + (lane & 7);
        const int kb = ((lane >> 3) & 1) * 16;
#pragma unroll
        for (int s = 0; s < 4; ++s) {
            const int ksb = s * 32;
            uint32_t Ah[MT][4], Bh[4][2], Bl[4][2];
#pragma unroll
            for (int mt = 0; mt < MT; ++mt) {
                const uint32_t off = (uint32_t)(wm0 + mt * 16 + ra) * 128 +
                                     (((uint32_t)(ksb + ka)) ^ xm);
                LDSM4(Ah[mt][0], Ah[mt][1], Ah[mt][2], Ah[mt][3], ab + off);
            }
#pragma unroll
            for (int p = 0; p < 2; ++p) {
                const uint32_t off = (uint32_t)(wn0 + p * 16 + rb) * 128 +
                                     (((uint32_t)(ksb + kb)) ^ xm);
                LDSM4(Bh[2 * p][0], Bh[2 * p][1], Bh[2 * p + 1][0], Bh[2 * p + 1][1], bb + off);
                LDSM4(Bl[2 * p][0], Bl[2 * p][1], Bl[2 * p + 1][0], Bl[2 * p + 1][1], blb + off);
            }
#pragma unroll
            for (int mt = 0; mt < MT; ++mt)
#pragma unroll
                for (int nt = 0; nt < 4; ++nt)
                    MMA16816(acc[mt][nt], Ah[mt], Bh[nt][0], Bh[nt][1]);
#pragma unroll
            for (int mt = 0; mt < MT; ++mt)
#pragma unroll
                for (int nt = 0; nt < 4; ++nt)
                    MMA16816(acc[mt][nt], Ah[mt], Bl[nt][0], Bl[nt][1]);
        }
    };

    // 2-stage double buffer: compute(c) then refill same buffer for c+2
    issue(0, 0);
    issue(1, 1);
    for (int c = 0; c < NC; ++c) {
        cp_wait<1>();
        __syncthreads();
        compute(c & 1);
        __syncthreads();
        if (c + 2 < NC) issue(c + 2, c & 1);
        else CP_COMMIT();
    }

    // epilogue
    const int g = lane >> 2, t = lane & 3;
#pragma unroll
    for (int mt = 0; mt < MT; ++mt) {
#pragma unroll
        for (int nt = 0; nt < 4; ++nt) {
            const int col = wn0 + nt * 8 + t * 2;
            float v0 = acc[mt][nt][0], v1 = acc[mt][nt][1];
            float v2 = acc[mt][nt][2], v3 = acc[mt][nt][3];
            const int row0 = m0 + wm0 + mt * 16 + g;
            if (EPI == 1) {
                const float bv0 = bias[col], bv1 = bias[col + 1];
                v0 += bv0; v1 += bv1; v2 += bv0; v3 += bv1;
                if (ACT == 1) { v0 = fmaxf(v0, 0.f); v1 = fmaxf(v1, 0.f); v2 = fmaxf(v2, 0.f); v3 = fmaxf(v3, 0.f); }
                if (ACT == 2) { v0 = tanhf(v0); v1 = tanhf(v1); v2 = tanhf(v2); v3 = tanhf(v3); }
                const size_t o0 = (size_t)zb * c_off + (size_t)row0 * ldc + n0g + col;
                const size_t o1 = (size_t)zb * c_off + (size_t)(row0 + 8) * ldc + n0g + col;
                *(uint32_t*)(Ch + o0) = packh2(v0, v1);
                *(uint32_t*)(Ch + o1) = packh2(v2, v3);
            } else {
                const int rem = N_STORE - n0g;
                const float bv0 = (col < rem) ? bias[col] : 0.f;
                const float bv1 = (col + 1 < rem) ? bias[col + 1] : 0.f;
                v0 += bv0; v1 += bv1; v2 += bv0; v3 += bv1;
                if (ACT == 1) { v0 = fmaxf(v0, 0.f); v1 = fmaxf(v1, 0.f); v2 = fmaxf(v2, 0.f); v3 = fmaxf(v3, 0.f); }
                if (ACT == 2) { v0 = tanhf(v0); v1 = tanhf(v1); v2 = tanhf(v2); v3 = tanhf(v3); }
                float* Cb = C + (size_t)zb * c_off + n0g;
                if (col < rem) {
                    Cb[(size_t)row0 * ldc + col] = v0;
                    Cb[(size_t)(row0 + 8) * ldc + col] = v2;
                }
                if (col + 1 < rem) {
                    Cb[(size_t)row0 * ldc + col + 1] = v1;
                    Cb[(size_t)(row0 + 8) * ldc + col + 1] = v3;
                }
            }
        }
    }
}

// ===================== rel = relu(fs * emb[idx]) -> fp16 plane =====================
__global__ void rel_kernel(const __half* __restrict__ fsp, const void* __restrict__ tidx,
                           const float* __restrict__ emb, __half* __restrict__ rp) {
    const int gid = blockIdx.x * blockDim.x + threadIdx.x;
    const int b = gid >> 7, h4 = (gid & 127) * 4;
    long long ti;
    if (d_is64) ti = ((const long long*)tidx)[b];
    else        ti = (long long)((const int*)tidx)[b];
    const size_t base = (size_t)b * Hn + h4;
    uint2 fu = *(const uint2*)(fsp + base);
    float2 f0 = h2f2(fu.x), f1 = h2f2(fu.y);
    float4 e = *(const float4*)(emb + (size_t)ti * Hn + h4);
    float r0 = fmaxf(f0.x * e.x, 0.f);
    float r1 = fmaxf(f0.y * e.y, 0.f);
    float r2 = fmaxf(f1.x * e.z, 0.f);
    float r3 = fmaxf(f1.y * e.w, 0.f);
    uint2 o;
    o.x = packh2(r0, r1);
    o.y = packh2(r2, r3);
    *(uint2*)(rp + base) = o;
}

// ===================== softmax over groups of 8 =====================
__global__ void softmax_kernel(float* __restrict__ pA, float* __restrict__ pC) {
    const int gid = blockIdx.x * blockDim.x + threadIdx.x;
    const int per = Bn * L1n * 8;
    float* p = (gid < per) ? (pA + (size_t)gid * 8) : (pC + (size_t)(gid - per) * 8);
    float v[8], mx = -1e30f;
#pragma unroll
    for (int j = 0; j < 8; j++) { v[j] = p[j]; mx = fmaxf(mx, v[j]); }
    float s = 0.f;
#pragma unroll
    for (int j = 0; j < 8; j++) { v[j] = __expf(v[j] - mx); s += v[j]; }
    const float inv = 1.f / s;
#pragma unroll
    for (int j = 0; j < 8; j++) p[j] = v[j] * inv;
}

// ===================== mix (fp16 planes) =====================
__global__ void mix_kernel(const float* __restrict__ probs,
                           const __half* __restrict__ op, __half* __restrict__ gp) {
    __shared__ float p[64];
    const int b = blockIdx.x, tid = threadIdx.x;
    if (tid < 64) p[tid] = probs[(size_t)b * (L1n * 64) + tid];
    __syncthreads();
    const size_t base = (size_t)b * 4096 + tid * 4;
    float o[8][4];
#pragma unroll
    for (int j = 0; j < 8; j++) {
        uint2 u = *(const uint2*)(op + base + j * 512);
        float2 a = h2f2(u.x), c = h2f2(u.y);
        o[j][0] = a.x; o[j][1] = a.y; o[j][2] = c.x; o[j][3] = c.y;
    }
#pragma unroll
    for (int i = 0; i < 8; i++) {
        float a0 = 0.f, a1 = 0.f, a2 = 0.f, a3 = 0.f;
#pragma unroll
        for (int j = 0; j < 8; j++) {
            const float w = p[i * 8 + j];
            a0 = fmaf(w, o[j][0], a0);
            a1 = fmaf(w, o[j][1], a1);
            a2 = fmaf(w, o[j][2], a2);
            a3 = fmaf(w, o[j][3], a3);
        }
        uint2 u;
        u.x = packh2(a0, a1);
        u.y = packh2(a2, a3);
        *(uint2*)(gp + base + i * 512) = u;
    }
}

// ===================== critic final =====================
__global__ void critic_kernel(const __half* __restrict__ gp, const float* __restrict__ wf,
                              float* __restrict__ val) {
    const int w = (blockIdx.x * blockDim.x + threadIdx.x) >> 5;
    const int lane = threadIdx.x & 31;
    const size_t off = (size_t)w * (Mn * Hn);
    float s = 0.f;
    for (int i = lane * 2; i < Mn * Hn; i += 64) {
        float2 g = h2f2(*(const uint32_t*)(gp + off + i));
        float2 f = *(const float2*)(wf + i);
        s = fmaf(g.x, f.x, s);
        s = fmaf(g.y, f.y, s);
    }
#pragma unroll
    for (int o = 16; o > 0; o >>= 1) s += __shfl_xor_sync(0xFFFFFFFFu, s, o);
    if (lane == 0) val[w] = s;
}

__global__ void prep_kernel(const float* __restrict__ abf, const float* __restrict__ cbf,
                            const float* __restrict__ logstd) {
    const int t = threadIdx.x;
    if (t < An) {
        float s = 0.f;
        for (int m = 0; m < Mn; m++) s += abf[m * An + t];
        d_cst[t] = s;
    }
    if (t == 17) {
        float s = 0.f;
        for (int m = 0; m < Mn; m++) s += cbf[m];
        d_cst[19] = s;
    }
    if (t == 18) {
        float lp = 0.f, en = 0.f;
        for (int a = 0; a < An; a++) {
            lp += -logstd[a] - LOGS2PI;
            en += 0.5f + LOGS2PI + logstd[a];
        }
        d_cst[17] = lp;
        d_cst[18] = en;
    }
}

__global__ void pack_kernel(const float* __restrict__ actorOut, const float* __restrict__ val,
                            float* __restrict__ out) {
    const int gid = blockIdx.x * blockDim.x + threadIdx.x;
    const int b = gid / 20, k = gid % 20;
    float v;
    if (k < An)        v = actorOut[(size_t)b * An + k];
    else if (k == 17)  v = d_cst[17];
    else if (k == 18)  v = d_cst[18];
    else               v = val[b] + d_cst[19];
    out[gid] = v;
}

// ===================== host =====================
extern "C" void kernel_launch(void* const* d_in, const int* in_sizes, int n_in,
                              void* d_out, int out_size) {
    const float* x      = (const float*)d_in[0];
    const void*  tidx   = d_in[1];
    const float* W1     = (const float*)d_in[2];
    const float* b1     = (const float*)d_in[3];
    const float* W2     = (const float*)d_in[4];
    const float* b2     = (const float*)d_in[5];
    const float* emb    = (const float*)d_in[6];
    const float* a_rW   = (const float*)d_in[7];
    const float* a_rb   = (const float*)d_in[8];
    const float* c_rW   = (const float*)d_in[9];
    const float* c_rb   = (const float*)d_in[10];
    const float* a_W    = (const float*)d_in[11];
    const float* a_b    = (const float*)d_in[12];
    const float* a_Wf   = (const float*)d_in[13];
    const float* a_bf   = (const float*)d_in[14];
    const float* c_W    = (const float*)d_in[15];
    const float* c_b    = (const float*)d_in[16];
    const float* c_Wf   = (const float*)d_in[17];
    const float* c_bf   = (const float*)d_in[18];
    const float* logstd = (const float*)d_in[19];
    float* out = (float*)d_out;

    float *pA, *pC, *actorOut, *val, *cst;
    __half *xp, *h1p, *fsp, *rp, *op, *g0p, *g1p, *g2p;
    __half *we1, *we2, *war, *wcr, *wa, *wc, *waf;
    cudaGetSymbolAddress((void**)&pA, d_probsA);
    cudaGetSymbolAddress((void**)&pC, d_probsC);
    cudaGetSymbolAddress((void**)&actorOut, d_actorOut);
    cudaGetSymbolAddress((void**)&val, d_val);
    cudaGetSymbolAddress((void**)&cst, d_cst);
    cudaGetSymbolAddress((void**)&xp, p_x);
    cudaGetSymbolAddress((void**)&h1p, p_h1);
    cudaGetSymbolAddress((void**)&fsp, p_fs);
    cudaGetSymbolAddress((void**)&rp, p_rel);
    cudaGetSymbolAddress((void**)&op, p_out);
    cudaGetSymbolAddress((void**)&g0p, p_g0);
    cudaGetSymbolAddress((void**)&g1p, p_g1);
    cudaGetSymbolAddress((void**)&g2p, p_g2);
    cudaGetSymbolAddress((void**)&we1, wt_e1);
    cudaGetSymbolAddress((void**)&we2, wt_e2);
    cudaGetSymbolAddress((void**)&war, wt_ar);
    cudaGetSymbolAddress((void**)&wcr, wt_cr);
    cudaGetSymbolAddress((void**)&wa, wt_a);
    cudaGetSymbolAddress((void**)&wc, wt_c);
    cudaGetSymbolAddress((void**)&waf, wt_af);

    // dynamic smem: 2 * (16384 + 2*NT*128)
    const int SM128 = 2 * (16384 + 2 * 128 * 128);  // 98304
    const int SM64  = 2 * (16384 + 2 * 64 * 128);   // 65536
    cudaFuncSetAttribute(mmagemm<128, 2, 1, 1>, cudaFuncAttributeMaxDynamicSharedMemorySize, SM128);
    cudaFuncSetAttribute(mmagemm<128, 2, 2, 1>, cudaFuncAttributeMaxDynamicSharedMemorySize, SM128);
    cudaFuncSetAttribute(mmagemm<64, 4, 0, 0>,  cudaFuncAttributeMaxDynamicSharedMemorySize, SM64);

    detect_kernel<<<1, 256>>>((const int*)tidx);
    splitx_kernel<<<(Bn * 96) / 256, 256>>>(x, xp);

    // weight conversion (transpose + fp16 hi/lo split)
    tconv_kernel<<<dim3(12, 16, 1),  dim3(32, 8)>>>(W1,   we1, OBSn, Hn, 384);
    tconv_kernel<<<dim3(16, 16, 1),  dim3(32, 8)>>>(W2,   we2, Hn,   Hn, 512);
    tconv_kernel<<<dim3(16, 2, 3),   dim3(32, 8)>>>(a_rW, war, Hn,   64, 512);
    tconv_kernel<<<dim3(16, 2, 3),   dim3(32, 8)>>>(c_rW, wcr, Hn,   64, 512);
    tconv_kernel<<<dim3(16, 16, 24), dim3(32, 8)>>>(a_W,  wa,  Hn,   Hn, 512);
    tconv_kernel<<<dim3(16, 16, 24), dim3(32, 8)>>>(c_W,  wc,  Hn,   Hn, 512);
    tconv_kernel<<<dim3(128, 2, 1),  dim3(32, 8)>>>(a_Wf, waf, Mn * Hn, An, 4096);

    // encoder
    mmagemm<128, 2, 2, 1><<<dim3(128, 4, 1), 256, SM128>>>(
        xp, 384, 0, we1, 384, 0, b1, 0,
        nullptr, h1p, Hn, 0, Hn, 6);
    mmagemm<128, 2, 2, 1><<<dim3(128, 4, 1), 256, SM128>>>(
        h1p, Hn, 0, we2, 512, 0, b2, 0,
        nullptr, fsp, Hn, 0, Hn, 8);
    rel_kernel<<<(Bn * 128) / 256, 256>>>(fsp, tidx, emb, rp);

    // routing (3 layers batched via grid z) -> fp32 probs
    mmagemm<64, 4, 0, 0><<<dim3(128, 1, 3), 256, SM64>>>(
        rp, Hn, 0, war, 512, 64 * 1024, a_rb, 64,
        pA, nullptr, L1n * 64, 64, 64, 8);
    mmagemm<64, 4, 0, 0><<<dim3(128, 1, 3), 256, SM64>>>(
        rp, Hn, 0, wcr, 512, 64 * 1024, c_rb, 64,
        pC, nullptr, L1n * 64, 64, 64, 8);
    softmax_kernel<<<(2 * Bn * L1n * 8) / 256, 256>>>(pA, pC);

    // critic chain: fs -> g0 -> g1 -> g2
    {
        const __half* gprev = fsp;
        __half* gs[3] = {g0p, g1p, g2p};
        for (int l = 0; l < L1n; l++) {
            mmagemm<128, 2, 1, 1><<<dim3(128, 4, 8), 256, SM128>>>(
                gprev, (l == 0) ? Hn : (Mn * Hn), (l == 0) ? 0 : Hn,
                wc + (size_t)l * Mn * 512 * 1024, 512, 512 * 1024,
                c_b + (size_t)l * Mn * Hn, Hn,
                nullptr, op, Mn * Hn, Hn, Hn, 8);
            mix_kernel<<<Bn, 128>>>(pC + (size_t)l * 64, op, gs[l]);
            gprev = gs[l];
        }
    }
    // actor chain: fs -> g0 -> g1 -> g0
    {
        const __half* gprev = fsp;
        __half* gs[3] = {g0p, g1p, g0p};
        for (int l = 0; l < L1n; l++) {
            mmagemm<128, 2, 1, 1><<<dim3(128, 4, 8), 256, SM128>>>(
                gprev, (l == 0) ? Hn : (Mn * Hn), (l == 0) ? 0 : Hn,
                wa + (size_t)l * Mn * 512 * 1024, 512, 512 * 1024,
                a_b + (size_t)l * Mn * Hn, Hn,
                nullptr, op, Mn * Hn, Hn, Hn, 8);
            mix_kernel<<<Bn, 128>>>(pA + (size_t)l * 64, op, gs[l]);
            gprev = gs[l];
        }
    }

    prep_kernel<<<1, 32>>>(a_bf, c_bf, logstd);
    // actor final: [B, 4096] @ [4096, 17] + summed bias
    mmagemm<64, 4, 0, 0><<<dim3(128, 1, 1), 256, SM64>>>(
        g0p, Mn * Hn, 0, waf, 4096, 0, cst, 0,
        actorOut, nullptr, An, 0, An, 64);
    critic_kernel<<<Bn / 8, 256>>>(g2p, c_Wf, val);
    pack_kernel<<<(Bn * 20) / 256, 256>>>(actorOut, val, out);
}

// round 7
// speedup vs baseline: 8.6750x; 1.4484x over previous
#include <cuda_runtime.h>
#include <cuda_fp16.h>
#include <math.h>
#include <stdint.h>

#define Bn   16384
#define OBSn 376
#define Hn   512
#define Mn   8
#define L1n  3
#define Tn   50
#define An   17
#define LOGS2PI 0.9189385332046727f

// ===================== helpers =====================
__device__ __forceinline__ uint32_t smem_to_u32(const void* p) {
    uint32_t a;
    asm("{ .reg .u64 t; cvta.to.shared.u64 t, %1; cvt.u32.u64 %0, t; }" : "=r"(a) : "l"(p));
    return a;
}
#define LDSM4(r0, r1, r2, r3, addr) \
    asm volatile("ldmatrix.sync.aligned.m8n8.x4.shared.b16 {%0,%1,%2,%3}, [%4];" \
        : "=r"(r0), "=r"(r1), "=r"(r2), "=r"(r3) : "r"(addr))
#define MMA16816(d, a, b0v, b1v) \
    asm volatile("mma.sync.aligned.m16n8k16.row.col.f32.f16.f16.f32 " \
        "{%0,%1,%2,%3}, {%4,%5,%6,%7}, {%8,%9}, {%0,%1,%2,%3};" \
        : "+f"((d)[0]), "+f"((d)[1]), "+f"((d)[2]), "+f"((d)[3]) \
        : "r"((a)[0]), "r"((a)[1]), "r"((a)[2]), "r"((a)[3]), "r"(b0v), "r"(b1v))
#define CP_ASYNC16(dst, src) \
    asm volatile("cp.async.cg.shared.global [%0], [%1], 16;" :: "r"(dst), "l"(src) : "memory")
#define CP_COMMIT() asm volatile("cp.async.commit_group;" ::: "memory")
template<int N> __device__ __forceinline__ void cp_wait() {
    asm volatile("cp.async.wait_group %0;" :: "n"(N) : "memory");
}

__device__ __forceinline__ uint32_t packh2(float a, float b) {
    __half2 h = __floats2half2_rn(a, b);
    return *reinterpret_cast<uint32_t*>(&h);
}
__device__ __forceinline__ float2 h2f2(uint32_t u) {
    __half2 h = *reinterpret_cast<__half2*>(&u);
    return __half22float2(h);
}

// ===================== scratch =====================
__device__ float d_probsA[(size_t)Bn * L1n * 64];
__device__ float d_probsC[(size_t)Bn * L1n * 64];
__device__ float d_actorOut[(size_t)Bn * An];
__device__ float d_val[Bn];
__device__ float d_cst[32];
__device__ int   d_is64;

// activation planes (single fp16)
__device__ __align__(16) __half p_x[(size_t)Bn * 384];
__device__ __align__(16) __half p_h1[(size_t)Bn * 512];
__device__ __align__(16) __half p_fs[(size_t)Bn * 512];
__device__ __align__(16) __half p_rel[(size_t)Bn * 512];
__device__ __align__(16) __half p_out[(size_t)Bn * 4096];
__device__ __align__(16) __half p_g0[(size_t)Bn * 4096];
__device__ __align__(16) __half p_g1[(size_t)Bn * 4096];
__device__ __align__(16) __half p_g2[(size_t)Bn * 4096];

// transposed weights: [slab][Nalloc][Kpad] fp16 (single plane)
__device__ __align__(16) __half wt_e1[(size_t)512 * 384];
__device__ __align__(16) __half wt_e2[(size_t)512 * 512];
__device__ __align__(16) __half wt_ar[(size_t)3 * 64 * 512];
__device__ __align__(16) __half wt_cr[(size_t)3 * 64 * 512];
__device__ __align__(16) __half wt_a[(size_t)24 * 512 * 512];
__device__ __align__(16) __half wt_c[(size_t)24 * 512 * 512];
__device__ __align__(16) __half wt_af[(size_t)64 * 4096];

// ===================== task_idx dtype detector =====================
__global__ void detect_kernel(const int* __restrict__ ti) {
    __shared__ int ok;
    if (threadIdx.x == 0) ok = 1;
    __syncthreads();
    for (int i = threadIdx.x; i < 1024; i += blockDim.x) {
        int v = ti[i];
        bool good = (i & 1) ? (v == 0) : (v >= 0 && v < Tn);
        if (!good) atomicAnd(&ok, 0);
    }
    __syncthreads();
    if (threadIdx.x == 0) d_is64 = ok;
}

// ===================== x -> fp16 plane (pad 376 -> 384) =====================
__global__ void splitx_kernel(const float* __restrict__ x, __half* __restrict__ xp) {
    const int gid = blockIdx.x * blockDim.x + threadIdx.x;  // Bn*96
    const int b = gid / 96, c4 = (gid % 96) * 4;
    float v[4];
#pragma unroll
    for (int e = 0; e < 4; ++e) {
        const int c = c4 + e;
        v[e] = (c < OBSn) ? x[(size_t)b * OBSn + c] : 0.f;
    }
    uint2 o;
    o.x = packh2(v[0], v[1]);
    o.y = packh2(v[2], v[3]);
    *(uint2*)(xp + (size_t)b * 384 + c4) = o;
}

// ===================== weight transpose -> fp16 =====================
__global__ void tconv_kernel(const float* __restrict__ W, __half* __restrict__ Wt,
                             int K, int Nsrc, int Kpad) {
    __shared__ float t[32][33];
    const int Nalloc = gridDim.y * 32;
    W  += (size_t)blockIdx.z * K * Nsrc;
    Wt += (size_t)blockIdx.z * Nalloc * Kpad;
    const int k0 = blockIdx.x * 32, n0 = blockIdx.y * 32;
    for (int i = threadIdx.y; i < 32; i += 8) {
        int k = k0 + i, n = n0 + threadIdx.x;
        t[i][threadIdx.x] = (k < K && n < Nsrc) ? W[(size_t)k * Nsrc + n] : 0.f;
    }
    __syncthreads();
    for (int i = threadIdx.y; i < 32; i += 8) {
        int n = n0 + i, k = k0 + threadIdx.x;
        if (k < Kpad)
            Wt[(size_t)n * Kpad + k] = __float2half_rn(t[threadIdx.x][i]);
    }
}

// ===================== mma.sync fp16 GEMM, 3-stage cp.async, 2 CTAs/SM =====================
// C = act(A @ B + bias). CTA 128 x NT, 8 warps, K chunk 64.
// Stage smem: A(16K) | B(NT*128).
template<int NT, int WARPS_M, int ACT, int EPI>  // EPI: 0 fp32 C, 1 fp16 plane
__global__ __launch_bounds__(256, 2) void mmagemm(
    const __half* __restrict__ A, int lda, long long a_off,
    const __half* __restrict__ Wt, int Kpad, long long w_bs,
    const float* __restrict__ bias, int b_bs,
    float* __restrict__ C, __half* __restrict__ Ch, int ldc, long long c_off,
    int N_STORE, int NC)
{
    extern __shared__ char smem[];
    const uint32_t sb = smem_to_u32(smem);
    const int tid = threadIdx.x, wid = tid >> 5, lane = tid & 31;
    const int m0 = blockIdx.x * 128;
    const int n0g = blockIdx.y * NT;
    const int zb = blockIdx.z;
    A    += (size_t)zb * a_off;
    Wt   += (size_t)zb * w_bs + (size_t)n0g * Kpad;
    bias += (size_t)zb * b_bs + n0g;

    constexpr int MT = 128 / (16 * WARPS_M);
    constexpr int BB = NT * 128;
    constexpr int STAGE = 16384 + BB;
    const int wm0 = (wid % WARPS_M) * (MT * 16);
    const int wn0 = (wid / WARPS_M) * 32;

    float acc[MT][4][4];
#pragma unroll
    for (int mt = 0; mt < MT; ++mt)
#pragma unroll
        for (int nt = 0; nt < 4; ++nt)
#pragma unroll
            for (int e = 0; e < 4; ++e) acc[mt][nt][e] = 0.f;

    auto issue = [&](int c, int buf) {
        const int k0 = c << 6;
        const uint32_t dbase = sb + buf * STAGE;
        // A: 128 rows x 64k fp16
#pragma unroll
        for (int it = 0; it < 4; ++it) {
            const int seg = it * 256 + tid;
            const int r = seg >> 3;
            const int ksb = (seg & 7) * 16;
            const int kelt = k0 + (seg & 7) * 8;
            const uint32_t doff = (uint32_t)r * 128 + ((uint32_t)ksb ^ (((uint32_t)r & 7) << 4));
            CP_ASYNC16(dbase + doff, A + (size_t)(m0 + r) * lda + kelt);
        }
        // B: NT rows x 64k fp16
#pragma unroll
        for (int it = 0; it < NT / 32; ++it) {
            const int seg = it * 256 + tid;
            const int r = seg >> 3;
            const int ksb = (seg & 7) * 16;
            const int kelt = k0 + (seg & 7) * 8;
            const uint32_t doff = (uint32_t)r * 128 + ((uint32_t)ksb ^ (((uint32_t)r & 7) << 4));
            CP_ASYNC16(dbase + 16384 + doff, Wt + (size_t)r * Kpad + kelt);
        }
        CP_COMMIT();
    };

    auto compute = [&](int buf) {
        const uint32_t ab = sb + buf * STAGE;
        const uint32_t bb = ab + 16384;
        const uint32_t xm = ((uint32_t)lane & 7) << 4;
        const int ra = ((lane >> 3) & 1) * 8 + (lane & 7);
        const int ka = ((lane >> 4) & 1) * 16;
        const int rb = ((lane >> 4) & 1) * 8 + (lane & 7);
        const int kb = ((lane >> 3) & 1) * 16;
#pragma unroll
        for (int s = 0; s < 4; ++s) {
            const int ksb = s * 32;
            uint32_t Ah[MT][4], Bh[4][2];
#pragma unroll
            for (int mt = 0; mt < MT; ++mt) {
                const uint32_t off = (uint32_t)(wm0 + mt * 16 + ra) * 128 +
                                     (((uint32_t)(ksb + ka)) ^ xm);
                LDSM4(Ah[mt][0], Ah[mt][1], Ah[mt][2], Ah[mt][3], ab + off);
            }
#pragma unroll
            for (int p = 0; p < 2; ++p) {
                const uint32_t off = (uint32_t)(wn0 + p * 16 + rb) * 128 +
                                     (((uint32_t)(ksb + kb)) ^ xm);
                LDSM4(Bh[2 * p][0], Bh[2 * p][1], Bh[2 * p + 1][0], Bh[2 * p + 1][1], bb + off);
            }
#pragma unroll
            for (int mt = 0; mt < MT; ++mt)
#pragma unroll
                for (int nt = 0; nt < 4; ++nt)
                    MMA16816(acc[mt][nt], Ah[mt], Bh[nt][0], Bh[nt][1]);
        }
    };

    // 3-stage pipeline: issue before compute each iteration
    issue(0, 0);
    issue(1, 1);
    for (int c = 0; c < NC; ++c) {
        cp_wait<1>();
        __syncthreads();
        if (c + 2 < NC) issue(c + 2, (c + 2) % 3);
        else CP_COMMIT();
        compute(c % 3);
        __syncthreads();
    }

    // epilogue
    const int g = lane >> 2, t = lane & 3;
#pragma unroll
    for (int mt = 0; mt < MT; ++mt) {
#pragma unroll
        for (int nt = 0; nt < 4; ++nt) {
            const int col = wn0 + nt * 8 + t * 2;
            float v0 = acc[mt][nt][0], v1 = acc[mt][nt][1];
            float v2 = acc[mt][nt][2], v3 = acc[mt][nt][3];
            const int row0 = m0 + wm0 + mt * 16 + g;
            if (EPI == 1) {
                const float bv0 = bias[col], bv1 = bias[col + 1];
                v0 += bv0; v1 += bv1; v2 += bv0; v3 += bv1;
                if (ACT == 1) { v0 = fmaxf(v0, 0.f); v1 = fmaxf(v1, 0.f); v2 = fmaxf(v2, 0.f); v3 = fmaxf(v3, 0.f); }
                if (ACT == 2) { v0 = tanhf(v0); v1 = tanhf(v1); v2 = tanhf(v2); v3 = tanhf(v3); }
                const size_t o0 = (size_t)zb * c_off + (size_t)row0 * ldc + n0g + col;
                const size_t o1 = (size_t)zb * c_off + (size_t)(row0 + 8) * ldc + n0g + col;
                *(uint32_t*)(Ch + o0) = packh2(v0, v1);
                *(uint32_t*)(Ch + o1) = packh2(v2, v3);
            } else {
                const int rem = N_STORE - n0g;
                const float bv0 = (col < rem) ? bias[col] : 0.f;
                const float bv1 = (col + 1 < rem) ? bias[col + 1] : 0.f;
                v0 += bv0; v1 += bv1; v2 += bv0; v3 += bv1;
                if (ACT == 1) { v0 = fmaxf(v0, 0.f); v1 = fmaxf(v1, 0.f); v2 = fmaxf(v2, 0.f); v3 = fmaxf(v3, 0.f); }
                if (ACT == 2) { v0 = tanhf(v0); v1 = tanhf(v1); v2 = tanhf(v2); v3 = tanhf(v3); }
                float* Cb = C + (size_t)zb * c_off + n0g;
                if (col < rem) {
                    Cb[(size_t)row0 * ldc + col] = v0;
                    Cb[(size_t)(row0 + 8) * ldc + col] = v2;
                }
                if (col + 1 < rem) {
                    Cb[(size_t)row0 * ldc + col + 1] = v1;
                    Cb[(size_t)(row0 + 8) * ldc + col + 1] = v3;
                }
            }
        }
    }
}

// ===================== rel = relu(fs * emb[idx]) -> fp16 plane =====================
__global__ void rel_kernel(const __half* __restrict__ fsp, const void* __restrict__ tidx,
                           const float* __restrict__ emb, __half* __restrict__ rp) {
    const int gid = blockIdx.x * blockDim.x + threadIdx.x;
    const int b = gid >> 7, h4 = (gid & 127) * 4;
    long long ti;
    if (d_is64) ti = ((const long long*)tidx)[b];
    else        ti = (long long)((const int*)tidx)[b];
    const size_t base = (size_t)b * Hn + h4;
    uint2 fu = *(const uint2*)(fsp + base);
    float2 f0 = h2f2(fu.x), f1 = h2f2(fu.y);
    float4 e = *(const float4*)(emb + (size_t)ti * Hn + h4);
    float r0 = fmaxf(f0.x * e.x, 0.f);
    float r1 = fmaxf(f0.y * e.y, 0.f);
    float r2 = fmaxf(f1.x * e.z, 0.f);
    float r3 = fmaxf(f1.y * e.w, 0.f);
    uint2 o;
    o.x = packh2(r0, r1);
    o.y = packh2(r2, r3);
    *(uint2*)(rp + base) = o;
}

// ===================== softmax over groups of 8 =====================
__global__ void softmax_kernel(float* __restrict__ pA, float* __restrict__ pC) {
    const int gid = blockIdx.x * blockDim.x + threadIdx.x;
    const int per = Bn * L1n * 8;
    float* p = (gid < per) ? (pA + (size_t)gid * 8) : (pC + (size_t)(gid - per) * 8);
    float v[8], mx = -1e30f;
#pragma unroll
    for (int j = 0; j < 8; j++) { v[j] = p[j]; mx = fmaxf(mx, v[j]); }
    float s = 0.f;
#pragma unroll
    for (int j = 0; j < 8; j++) { v[j] = __expf(v[j] - mx); s += v[j]; }
    const float inv = 1.f / s;
#pragma unroll
    for (int j = 0; j < 8; j++) p[j] = v[j] * inv;
}

// ===================== mix (fp16 planes) =====================
__global__ void mix_kernel(const float* __restrict__ probs,
                           const __half* __restrict__ op, __half* __restrict__ gp) {
    __shared__ float p[64];
    const int b = blockIdx.x, tid = threadIdx.x;
    if (tid < 64) p[tid] = probs[(size_t)b * (L1n * 64) + tid];
    __syncthreads();
    const size_t base = (size_t)b * 4096 + tid * 4;
    float o[8][4];
#pragma unroll
    for (int j = 0; j < 8; j++) {
        uint2 u = *(const uint2*)(op + base + j * 512);
        float2 a = h2f2(u.x), c = h2f2(u.y);
        o[j][0] = a.x; o[j][1] = a.y; o[j][2] = c.x; o[j][3] = c.y;
    }
#pragma unroll
    for (int i = 0; i < 8; i++) {
        float a0 = 0.f, a1 = 0.f, a2 = 0.f, a3 = 0.f;
#pragma unroll
        for (int j = 0; j < 8; j++) {
            const float w = p[i * 8 + j];
            a0 = fmaf(w, o[j][0], a0);
            a1 = fmaf(w, o[j][1], a1);
            a2 = fmaf(w, o[j][2], a2);
            a3 = fmaf(w, o[j][3], a3);
        }
        uint2 u;
        u.x = packh2(a0, a1);
        u.y = packh2(a2, a3);
        *(uint2*)(gp + base + i * 512) = u;
    }
}

// ===================== critic final =====================
__global__ void critic_kernel(const __half* __restrict__ gp, const float* __restrict__ wf,
                              float* __restrict__ val) {
    const int w = (blockIdx.x * blockDim.x + threadIdx.x) >> 5;
    const int lane = threadIdx.x & 31;
    const size_t off = (size_t)w * (Mn * Hn);
    float s = 0.f;
    for (int i = lane * 2; i < Mn * Hn; i += 64) {
        float2 g = h2f2(*(const uint32_t*)(gp + off + i));
        float2 f = *(const float2*)(wf + i);
        s = fmaf(g.x, f.x, s);
        s = fmaf(g.y, f.y, s);
    }
#pragma unroll
    for (int o = 16; o > 0; o >>= 1) s += __shfl_xor_sync(0xFFFFFFFFu, s, o);
    if (lane == 0) val[w] = s;
}

__global__ void prep_kernel(const float* __restrict__ abf, const float* __restrict__ cbf,
                            const float* __restrict__ logstd) {
    const int t = threadIdx.x;
    if (t < An) {
        float s = 0.f;
        for (int m = 0; m < Mn; m++) s += abf[m * An + t];
        d_cst[t] = s;
    }
    if (t == 17) {
        float s = 0.f;
        for (int m = 0; m < Mn; m++) s += cbf[m];
        d_cst[19] = s;
    }
    if (t == 18) {
        float lp = 0.f, en = 0.f;
        for (int a = 0; a < An; a++) {
            lp += -logstd[a] - LOGS2PI;
            en += 0.5f + LOGS2PI + logstd[a];
        }
        d_cst[17] = lp;
        d_cst[18] = en;
    }
}

__global__ void pack_kernel(const float* __restrict__ actorOut, const float* __restrict__ val,
                            float* __restrict__ out) {
    const int gid = blockIdx.x * blockDim.x + threadIdx.x;
    const int b = gid / 20, k = gid % 20;
    float v;
    if (k < An)        v = actorOut[(size_t)b * An + k];
    else if (k == 17)  v = d_cst[17];
    else if (k == 18)  v = d_cst[18];
    else               v = val[b] + d_cst[19];
    out[gid] = v;
}

// ===================== host =====================
extern "C" void kernel_launch(void* const* d_in, const int* in_sizes, int n_in,
                              void* d_out, int out_size) {
    const float* x      = (const float*)d_in[0];
    const void*  tidx   = d_in[1];
    const float* W1     = (const float*)d_in[2];
    const float* b1     = (const float*)d_in[3];
    const float* W2     = (const float*)d_in[4];
    const float* b2     = (const float*)d_in[5];
    const float* emb    = (const float*)d_in[6];
    const float* a_rW   = (const float*)d_in[7];
    const float* a_rb   = (const float*)d_in[8];
    const float* c_rW   = (const float*)d_in[9];
    const float* c_rb   = (const float*)d_in[10];
    const float* a_W    = (const float*)d_in[11];
    const float* a_b    = (const float*)d_in[12];
    const float* a_Wf   = (const float*)d_in[13];
    const float* a_bf   = (const float*)d_in[14];
    const float* c_W    = (const float*)d_in[15];
    const float* c_b    = (const float*)d_in[16];
    const float* c_Wf   = (const float*)d_in[17];
    const float* c_bf   = (const float*)d_in[18];
    const float* logstd = (const float*)d_in[19];
    float* out = (float*)d_out;

    float *pA, *pC, *actorOut, *val, *cst;
    __half *xp, *h1p, *fsp, *rp, *op, *g0p, *g1p, *g2p;
    __half *we1, *we2, *war, *wcr, *wa, *wc, *waf;
    cudaGetSymbolAddress((void**)&pA, d_probsA);
    cudaGetSymbolAddress((void**)&pC, d_probsC);
    cudaGetSymbolAddress((void**)&actorOut, d_actorOut);
    cudaGetSymbolAddress((void**)&val, d_val);
    cudaGetSymbolAddress((void**)&cst, d_cst);
    cudaGetSymbolAddress((void**)&xp, p_x);
    cudaGetSymbolAddress((void**)&h1p, p_h1);
    cudaGetSymbolAddress((void**)&fsp, p_fs);
    cudaGetSymbolAddress((void**)&rp, p_rel);
    cudaGetSymbolAddress((void**)&op, p_out);
    cudaGetSymbolAddress((void**)&g0p, p_g0);
    cudaGetSymbolAddress((void**)&g1p, p_g1);
    cudaGetSymbolAddress((void**)&g2p, p_g2);
    cudaGetSymbolAddress((void**)&we1, wt_e1);
    cudaGetSymbolAddress((void**)&we2, wt_e2);
    cudaGetSymbolAddress((void**)&war, wt_ar);
    cudaGetSymbolAddress((void**)&wcr, wt_cr);
    cudaGetSymbolAddress((void**)&wa, wt_a);
    cudaGetSymbolAddress((void**)&wc, wt_c);
    cudaGetSymbolAddress((void**)&waf, wt_af);

    // dynamic smem: 3 * (16384 + NT*128)
    const int SM128 = 3 * (16384 + 128 * 128);  // 98304
    const int SM64  = 3 * (16384 + 64 * 128);   // 73728
    cudaFuncSetAttribute(mmagemm<128, 2, 1, 1>, cudaFuncAttributeMaxDynamicSharedMemorySize, SM128);
    cudaFuncSetAttribute(mmagemm<128, 2, 2, 1>, cudaFuncAttributeMaxDynamicSharedMemorySize, SM128);
    cudaFuncSetAttribute(mmagemm<64, 4, 0, 0>,  cudaFuncAttributeMaxDynamicSharedMemorySize, SM64);

    detect_kernel<<<1, 256>>>((const int*)tidx);
    splitx_kernel<<<(Bn * 96) / 256, 256>>>(x, xp);

    // weight conversion (transpose -> fp16, [N][Kpad])
    tconv_kernel<<<dim3(12, 16, 1),  dim3(32, 8)>>>(W1,   we1, OBSn, Hn, 384);
    tconv_kernel<<<dim3(16, 16, 1),  dim3(32, 8)>>>(W2,   we2, Hn,   Hn, 512);
    tconv_kernel<<<dim3(16, 2, 3),   dim3(32, 8)>>>(a_rW, war, Hn,   64, 512);
    tconv_kernel<<<dim3(16, 2, 3),   dim3(32, 8)>>>(c_rW, wcr, Hn,   64, 512);
    tconv_kernel<<<dim3(16, 16, 24), dim3(32, 8)>>>(a_W,  wa,  Hn,   Hn, 512);
    tconv_kernel<<<dim3(16, 16, 24), dim3(32, 8)>>>(c_W,  wc,  Hn,   Hn, 512);
    tconv_kernel<<<dim3(128, 2, 1),  dim3(32, 8)>>>(a_Wf, waf, Mn * Hn, An, 4096);

    // encoder
    mmagemm<128, 2, 2, 1><<<dim3(128, 4, 1), 256, SM128>>>(
        xp, 384, 0, we1, 384, 0, b1, 0,
        nullptr, h1p, Hn, 0, Hn, 6);
    mmagemm<128, 2, 2, 1><<<dim3(128, 4, 1), 256, SM128>>>(
        h1p, Hn, 0, we2, 512, 0, b2, 0,
        nullptr, fsp, Hn, 0, Hn, 8);
    rel_kernel<<<(Bn * 128) / 256, 256>>>(fsp, tidx, emb, rp);

    // routing (3 layers batched via grid z) -> fp32 probs
    mmagemm<64, 4, 0, 0><<<dim3(128, 1, 3), 256, SM64>>>(
        rp, Hn, 0, war, 512, 64 * 512, a_rb, 64,
        pA, nullptr, L1n * 64, 64, 64, 8);
    mmagemm<64, 4, 0, 0><<<dim3(128, 1, 3), 256, SM64>>>(
        rp, Hn, 0, wcr, 512, 64 * 512, c_rb, 64,
        pC, nullptr, L1n * 64, 64, 64, 8);
    softmax_kernel<<<(2 * Bn * L1n * 8) / 256, 256>>>(pA, pC);

    // critic chain: fs -> g0 -> g1 -> g2
    {
        const __half* gprev = fsp;
        __half* gs[3] = {g0p, g1p, g2p};
        for (int l = 0; l < L1n; l++) {
            mmagemm<128, 2, 1, 1><<<dim3(128, 4, 8), 256, SM128>>>(
                gprev, (l == 0) ? Hn : (Mn * Hn), (l == 0) ? 0 : Hn,
                wc + (size_t)l * Mn * 512 * 512, 512, 512 * 512,
                c_b + (size_t)l * Mn * Hn, Hn,
                nullptr, op, Mn * Hn, Hn, Hn, 8);
            mix_kernel<<<Bn, 128>>>(pC + (size_t)l * 64, op, gs[l]);
            gprev = gs[l];
        }
    }
    // actor chain: fs -> g0 -> g1 -> g0
    {
        const __half* gprev = fsp;
        __half* gs[3] = {g0p, g1p, g0p};
        for (int l = 0; l < L1n; l++) {
            mmagemm<128, 2, 1, 1><<<dim3(128, 4, 8), 256, SM128>>>(
                gprev, (l == 0) ? Hn : (Mn * Hn), (l == 0) ? 0 : Hn,
                wa + (size_t)l * Mn * 512 * 512, 512, 512 * 512,
                a_b + (size_t)l * Mn * Hn, Hn,
                nullptr, op, Mn * Hn, Hn, Hn, 8);
            mix_kernel<<<Bn, 128>>>(pA + (size_t)l * 64, op, gs[l]);
            gprev = gs[l];
        }
    }

    prep_kernel<<<1, 32>>>(a_bf, c_bf, logstd);
    // actor final: [B, 4096] @ [4096, 17] + summed bias
    mmagemm<64, 4, 0, 0><<<dim3(128, 1, 1), 256, SM64>>>(
        g0p, Mn * Hn, 0, waf, 4096, 0, cst, 0,
        actorOut, nullptr, An, 0, An, 64);
    critic_kernel<<<Bn / 8, 256>>>(g2p, c_Wf, val);
    pack_kernel<<<(Bn * 20) / 256, 256>>>(actorOut, val, out);
}